// round 14
// baseline (speedup 1.0000x reference)
#include <cuda_runtime.h>
#include <cuda_fp16.h>
#include <cstdint>

// ============================================================================
// Problem constants
// ============================================================================
#define N_NODES 961
#define N_EDGES 32768
#define WIDTH   64
#define KDIM    1024
#define N3      4096   // WIDTH*WIDTH
#define MPAD    1024   // padded node count for T-GEMM
#define NT2     65536  // 64*1024 (o,j) pairs
#define MAX_TILES 1473 // <= N_NODES + N_EDGES/64
#define HALF_NODES 512 // node-split point for depth-loop pipelining

// ============================================================================
// Device scratch (sanctioned: __device__ globals, no runtime allocation)
// ============================================================================
__device__ __half g_h1h[(size_t)N_EDGES * KDIM];         //  64 MB
__device__ __half g_h1l[(size_t)N_EDGES * KDIM];         //  64 MB
__device__ __half g_h2h[(size_t)N_EDGES * KDIM];         //  64 MB
__device__ __half g_h2l[(size_t)N_EDGES * KDIM];         //  64 MB
__device__ __half g_Th [(size_t)MPAD * NT2];             // 128 MB  T[n][o][j] hi
__device__ __half g_Tl [(size_t)MPAD * NT2];             // 128 MB  T[n][o][j] lo
__device__ __half g_w2th[(size_t)KDIM * KDIM];           //   2 MB
__device__ __half g_w2tl[(size_t)KDIM * KDIM];           //   2 MB
__device__ __half g_k3th[(size_t)NT2 * WIDTH];           //   8 MB  k3tt2 hi
__device__ __half g_k3tl[(size_t)NT2 * WIDTH];           //   8 MB
__device__ __half g_zph[MPAD * WIDTH];
__device__ __half g_zpl[MPAD * WIDTH];
__device__ float  g_Bz [N_NODES * WIDTH];
__device__ float  g_z  [N_NODES * WIDTH];
__device__ float  g_agg[N_NODES * WIDTH];
__device__ float  g_cnt[N_NODES];
__device__ float  g_invcnt[N_NODES];
__device__ int    g_src[N_EDGES];
__device__ int    g_dst[N_EDGES];
__device__ int    g_srccnt[N_NODES];
__device__ int    g_scur[N_NODES];
__device__ int    g_srcptr[N_NODES + 1];
__device__ int    g_tileptr[N_NODES + 1];
__device__ int    g_eord[N_EDGES];
__device__ int    g_tilemap[MAX_TILES];
__device__ int    g_ntiles;
__device__ int    g_flag;

// ============================================================================
// PTX helpers (compute_100-safe: cp.async / ldmatrix / mma.sync only)
// ============================================================================
__device__ __forceinline__ uint32_t smem_u32(const void* smem_ptr) {
    uint32_t addr;
    asm("{ .reg .u64 tmp; cvta.to.shared.u64 tmp, %1; cvt.u32.u64 %0, tmp; }"
        : "=r"(addr) : "l"(smem_ptr));
    return addr;
}

__device__ __forceinline__ void cp_async16(uint32_t saddr, const void* gaddr) {
    asm volatile("cp.async.cg.shared.global [%0], [%1], 16;\n"
                 :: "r"(saddr), "l"(gaddr));
}
// Predicated: src_size=0 -> zero-fill the 16B destination.
__device__ __forceinline__ void cp_async16_pred(uint32_t saddr, const void* gaddr,
                                                int src_size) {
    asm volatile("cp.async.cg.shared.global [%0], [%1], 16, %2;\n"
                 :: "r"(saddr), "l"(gaddr), "r"(src_size));
}
__device__ __forceinline__ void cp_async_commit() {
    asm volatile("cp.async.commit_group;\n" ::: "memory");
}
template <int N>
__device__ __forceinline__ void cp_async_wait() {
    asm volatile("cp.async.wait_group %0;\n" :: "n"(N) : "memory");
}

#define LDSM4(r0, r1, r2, r3, addr) \
    asm volatile("ldmatrix.sync.aligned.m8n8.x4.shared.b16 {%0,%1,%2,%3}, [%4];" \
                 : "=r"(r0), "=r"(r1), "=r"(r2), "=r"(r3) : "r"(addr))

__device__ __forceinline__ void mma_16816(float* c, const uint32_t* a,
                                          uint32_t b0, uint32_t b1) {
    asm volatile(
        "mma.sync.aligned.m16n8k16.row.col.f32.f16.f16.f32 "
        "{%0,%1,%2,%3}, {%4,%5,%6,%7}, {%8,%9}, {%0,%1,%2,%3};"
        : "+f"(c[0]), "+f"(c[1]), "+f"(c[2]), "+f"(c[3])
        : "r"(a[0]), "r"(a[1]), "r"(a[2]), "r"(a[3]), "r"(b0), "r"(b1));
}

// ============================================================================
// Setup kernels
// ============================================================================

// h1 = relu(edge_attr @ k_w1 + b1), split hi/lo fp16 out
__global__ void l1_kernel(const float* __restrict__ attr,
                          const float* __restrict__ w1,
                          const float* __restrict__ b1) {
    int e = blockIdx.x;
    __shared__ float a[6];
    if (threadIdx.x < 6) a[threadIdx.x] = attr[e * 6 + threadIdx.x];
    __syncthreads();
    for (int j = threadIdx.x; j < KDIM; j += blockDim.x) {
        float acc = b1[j];
        #pragma unroll
        for (int i = 0; i < 6; i++) acc += a[i] * w1[i * KDIM + j];
        acc = fmaxf(acc, 0.f);
        __half hi = __float2half_rn(acc);
        g_h1h[(size_t)e * KDIM + j] = hi;
        g_h1l[(size_t)e * KDIM + j] = __float2half_rn(acc - __half2float(hi));
    }
}

// Detect whether edge_index buffer is int64 or int32.
__global__ void detect_kernel(const void* ei) {
    if (threadIdx.x == 0 && blockIdx.x == 0) {
        const long long* p = (const long long*)ei;
        int ok = 1;
        for (int i = 0; i < 64; i++) {
            long long v = p[i];
            if (v < 0 || v >= N_NODES) { ok = 0; break; }
        }
        g_flag = ok;   // 1 => int64, 0 => int32
    }
}

// w2t hi/lo: dst[n*1024 + k] = split( kw2[k*1024 + n] )
__global__ void cast_w2_kernel(const float* __restrict__ src) {
    int i = blockIdx.x * blockDim.x + threadIdx.x;
    if (i >= KDIM * KDIM) return;
    int n = i >> 10;
    int k = i & 1023;
    float v = src[k * KDIM + n];
    __half hi = __float2half_rn(v);
    g_w2th[i] = hi;
    g_w2tl[i] = __float2half_rn(v - __half2float(hi));
}

// Zero counters + compute z0 = x@fc1 + b.
__global__ void zero_z0_kernel(const float* __restrict__ x,
                               const float* __restrict__ w,
                               const float* __restrict__ b) {
    int i = blockIdx.x * blockDim.x + threadIdx.x;
    if (i < N_NODES) {
        g_cnt[i] = 0.f;
        g_srccnt[i] = 0;
        g_scur[i] = 0;
    }
    if (i < N_NODES * WIDTH) {
        int n = i >> 6, j = i & 63;
        g_agg[i] = 0.f;
        g_z[i] = x[n] * w[j] + b[j];
    }
}

// k3tt2 hi/lo (o-major): row r2 = o*1024 + j, col i:
//   k3tt2[r2*64 + i] = kw3[j*4096 + i*64 + o]
__global__ void k3tt2_kernel(const float* __restrict__ kw3) {
    int idx = blockIdx.x * blockDim.x + threadIdx.x;  // < 65536*64
    int r2 = idx >> 6;
    int i = idx & 63;
    int o = r2 >> 10;
    int j = r2 & 1023;
    float v = kw3[(size_t)j * N3 + i * 64 + o];
    __half hi = __float2half_rn(v);
    g_k3th[idx] = hi;
    g_k3tl[idx] = __float2half_rn(v - __half2float(hi));
}

// Decode edge_index, count dst (for mean) and src (for CSR).
__global__ void decode_count_kernel(const void* ei) {
    int e = blockIdx.x * blockDim.x + threadIdx.x;
    if (e >= N_EDGES) return;
    int s, d;
    if (g_flag) {
        const long long* p = (const long long*)ei;
        s = (int)p[e];
        d = (int)p[N_EDGES + e];
    } else {
        const int* p = (const int*)ei;
        s = p[e];
        d = p[N_EDGES + e];
    }
    g_src[e] = s;
    g_dst[e] = d;
    atomicAdd(&g_cnt[d], 1.0f);
    atomicAdd(&g_srccnt[s], 1);
}

// Scans: srccnt -> srcptr (exclusive), invcnt; 64-edge tile counts -> tileptr.
__global__ void scan_kernel() {
    __shared__ int s[1024];
    int tid = threadIdx.x;
    int v = (tid < N_NODES) ? g_srccnt[tid] : 0;
    s[tid] = v;
    __syncthreads();
    #pragma unroll
    for (int off = 1; off < 1024; off <<= 1) {
        int t = (tid >= off) ? s[tid - off] : 0;
        __syncthreads();
        s[tid] += t;
        __syncthreads();
    }
    if (tid < N_NODES) {
        g_srcptr[tid] = s[tid] - v;
        g_invcnt[tid] = 1.0f / fmaxf(g_cnt[tid], 1.0f);
    }
    if (tid == 0) g_srcptr[N_NODES] = N_EDGES;
    __syncthreads();

    int tc = (tid < N_NODES) ? ((v + 63) >> 6) : 0;
    s[tid] = tc;
    __syncthreads();
    #pragma unroll
    for (int off = 1; off < 1024; off <<= 1) {
        int t = (tid >= off) ? s[tid - off] : 0;
        __syncthreads();
        s[tid] += t;
        __syncthreads();
    }
    if (tid < N_NODES) g_tileptr[tid] = s[tid] - tc;
    if (tid == 1023) {
        g_tileptr[N_NODES] = s[1023];
        g_ntiles = s[1023];
    }
}

// Scatter edges into src-sorted order; fill tile map.
__global__ void scatter_kernel() {
    int e = blockIdx.x * blockDim.x + threadIdx.x;
    if (e >= N_EDGES) return;
    int s = g_src[e];
    int pos = g_srcptr[s] + atomicAdd(&g_scur[s], 1);
    g_eord[pos] = e;
}
__global__ void tilefill_kernel() {
    int n = blockIdx.x;
    int tp = g_tileptr[n];
    int tc = g_tileptr[n + 1] - tp;
    for (int t = threadIdx.x; t < tc; t += blockDim.x)
        g_tilemap[tp + t] = n | (t << 16);
}

// ============================================================================
// Split-fp16 3-pass GEMM:  C(hi,lo) = act(A @ BT^T [+ bias])
//   C = A_hi*B_hi + A_hi*B_lo + A_lo*B_hi  (fp32 accum), out split to fp16 pair
// CTA tile 128x128xBK32, 2-stage cp.async, 256 threads (4m x 2n).
// SINGLE_SYNC=true : single-barrier loop (best for 2-CTA/SM GEMM1 regime)
// SINGLE_SYNC=false: classic double-barrier loop (best for many-wave T-GEMM)
// ============================================================================
#define BM 128
#define BN 128
#define BK 32
#define LDA 40
#define STAGE_HALFS (512 * LDA)
#define STAGE_BYTES (STAGE_HALFS * 2) // 40960
#define GEMM_DSMEM (2 * STAGE_BYTES)  // 81920

#define OFF_AL (128 * LDA * 2)
#define OFF_BH (256 * LDA * 2)
#define OFF_BL (384 * LDA * 2)

template <bool SINGLE_SYNC>
__global__ void __launch_bounds__(256) gemm_split_kernel(
        const __half* __restrict__ Ah, const __half* __restrict__ Al,
        const __half* __restrict__ Bh, const __half* __restrict__ Bl,
        __half* __restrict__ Ch, __half* __restrict__ Cl,
        const float* __restrict__ bias, int N, int K, int relu) {
    extern __shared__ __align__(16) __half sm[];

    const int tid  = threadIdx.x;
    const int lane = tid & 31;
    const int wid  = tid >> 5;
    const int wm   = wid & 3;
    const int wn   = wid >> 2;
    const int bn   = blockIdx.x;
    const int bm   = blockIdx.y;

    const uint32_t sbase = smem_u32(sm);

    const int crow = tid >> 2;
    const int ccol = (tid & 3) * 8;
    const size_t arow = (size_t)(bm * BM + crow) * K + ccol;
    const __half* gAh0 = Ah + arow;
    const __half* gAh1 = gAh0 + (size_t)64 * K;
    const __half* gAl0 = Al + arow;
    const __half* gAl1 = gAl0 + (size_t)64 * K;
    const size_t brow = (size_t)(bn * BN + crow) * K + ccol;
    const __half* gBh0 = Bh + brow;
    const __half* gBh1 = gBh0 + (size_t)64 * K;
    const __half* gBl0 = Bl + brow;
    const __half* gBl1 = gBl0 + (size_t)64 * K;
    uint32_t so_[8];
    #pragma unroll
    for (int r = 0; r < 8; r++)
        so_[r] = ((crow + r * 64) * LDA + ccol) * 2;

    uint32_t aoff[2];
    #pragma unroll
    for (int mt = 0; mt < 2; mt++) {
        int r = wm * 32 + mt * 16 + (lane & 15);
        int c = (lane >> 4) << 3;
        aoff[mt] = (r * LDA + c) * 2;
    }
    uint32_t boff[4];
    #pragma unroll
    for (int tp = 0; tp < 4; tp++) {
        int r = wn * 64 + tp * 16 + ((lane >> 4) << 3) + (lane & 7);
        int c = ((lane >> 3) & 1) * 8;
        boff[tp] = OFF_BH + (r * LDA + c) * 2;
    }

    float acc[2][8][4];
    #pragma unroll
    for (int mt = 0; mt < 2; mt++)
        #pragma unroll
        for (int nt = 0; nt < 8; nt++)
            #pragma unroll
            for (int i = 0; i < 4; i++) acc[mt][nt][i] = 0.f;

    const int nkt = K / BK;

    #define G_LOAD(st, kt) do { \
        uint32_t so = sbase + (st) * STAGE_BYTES; \
        int go = (kt) * BK; \
        cp_async16(so + so_[0], gAh0 + go); \
        cp_async16(so + so_[1], gAh1 + go); \
        cp_async16(so + so_[2], gAl0 + go); \
        cp_async16(so + so_[3], gAl1 + go); \
        cp_async16(so + so_[4], gBh0 + go); \
        cp_async16(so + so_[5], gBh1 + go); \
        cp_async16(so + so_[6], gBl0 + go); \
        cp_async16(so + so_[7], gBl1 + go); \
    } while (0)

    G_LOAD(0, 0);
    cp_async_commit();

    for (int kt = 0; kt < nkt; kt++) {
        if (SINGLE_SYNC) {
            cp_async_wait<0>();
            __syncthreads();
            if (kt + 1 < nkt) {
                G_LOAD((kt + 1) & 1, kt + 1);
                cp_async_commit();
            }
        } else {
            if (kt + 1 < nkt) {
                G_LOAD((kt + 1) & 1, kt + 1);
                cp_async_commit();
                cp_async_wait<1>();
            } else {
                cp_async_wait<0>();
            }
            __syncthreads();
        }

        const uint32_t sb = sbase + (kt & 1) * STAGE_BYTES;
        #pragma unroll
        for (int kk = 0; kk < 2; kk++) {
            uint32_t ah[2][4], al[2][4];
            #pragma unroll
            for (int mt = 0; mt < 2; mt++) {
                LDSM4(ah[mt][0], ah[mt][1], ah[mt][2], ah[mt][3],
                      sb + aoff[mt] + kk * 32);
                LDSM4(al[mt][0], al[mt][1], al[mt][2], al[mt][3],
                      sb + OFF_AL + aoff[mt] + kk * 32);
            }
            uint32_t bh[4][4], bl[4][4];
            #pragma unroll
            for (int tp = 0; tp < 4; tp++) {
                LDSM4(bh[tp][0], bh[tp][1], bh[tp][2], bh[tp][3],
                      sb + boff[tp] + kk * 32);
                LDSM4(bl[tp][0], bl[tp][1], bl[tp][2], bl[tp][3],
                      sb + (OFF_BL - OFF_BH) + boff[tp] + kk * 32);
            }
            #pragma unroll
            for (int mt = 0; mt < 2; mt++)
                #pragma unroll
                for (int nt = 0; nt < 8; nt++) {
                    const uint32_t* bhp = bh[nt >> 1];
                    const uint32_t* blp = bl[nt >> 1];
                    uint32_t h0, h1, l0, l1;
                    if (nt & 1) { h0 = bhp[2]; h1 = bhp[3]; l0 = blp[2]; l1 = blp[3]; }
                    else        { h0 = bhp[0]; h1 = bhp[1]; l0 = blp[0]; l1 = blp[1]; }
                    mma_16816(acc[mt][nt], ah[mt], h0, h1);
                    mma_16816(acc[mt][nt], ah[mt], l0, l1);
                    mma_16816(acc[mt][nt], al[mt], h0, h1);
                }
        }
        if (!SINGLE_SYNC) __syncthreads();
    }
    #undef G_LOAD

    #pragma unroll
    for (int mt = 0; mt < 2; mt++) {
        int r0 = bm * BM + wm * 32 + mt * 16 + (lane >> 2);
        #pragma unroll
        for (int nt = 0; nt < 8; nt++) {
            int col = bn * BN + wn * 64 + nt * 8 + (lane & 3) * 2;
            float b0 = 0.f, b1 = 0.f;
            if (bias) { b0 = __ldg(bias + col); b1 = __ldg(bias + col + 1); }
            float v[4];
            v[0] = acc[mt][nt][0] + b0;
            v[1] = acc[mt][nt][1] + b1;
            v[2] = acc[mt][nt][2] + b0;
            v[3] = acc[mt][nt][3] + b1;
            if (relu) {
                v[0] = fmaxf(v[0], 0.f); v[1] = fmaxf(v[1], 0.f);
                v[2] = fmaxf(v[2], 0.f); v[3] = fmaxf(v[3], 0.f);
            }
            __half h0 = __float2half_rn(v[0]), h1 = __float2half_rn(v[1]);
            __half h2v = __float2half_rn(v[2]), h3 = __float2half_rn(v[3]);
            size_t o0 = (size_t)r0 * N + col;
            size_t o1 = (size_t)(r0 + 8) * N + col;
            *(__half2*)(Ch + o0) = __halves2half2(h0, h1);
            *(__half2*)(Ch + o1) = __halves2half2(h2v, h3);
            *(__half2*)(Cl + o0) = __halves2half2(
                __float2half_rn(v[0] - __half2float(h0)),
                __float2half_rn(v[1] - __half2float(h1)));
            *(__half2*)(Cl + o1) = __halves2half2(
                __float2half_rn(v[2] - __half2float(h2v)),
                __float2half_rn(v[3] - __half2float(h3)));
        }
    }
}

// ============================================================================
// Depth-loop kernels
// ============================================================================

// Split z into padded hi/lo fp16 (rows >= N_NODES -> 0). Initial use only.
__global__ void zsplit_kernel() {
    int i = blockIdx.x * blockDim.x + threadIdx.x;
    if (i >= MPAD * WIDTH) return;
    int n = i >> 6;
    float v = (n < N_NODES) ? g_z[i] : 0.f;
    __half hi = __float2half_rn(v);
    g_zph[i] = hi;
    g_zpl[i] = __float2half_rn(v - __half2float(hi));
}

// Bz[n,o] = sum_i z[n,i] * b3[i*64+o]. Initial use only.
__global__ void bz_kernel(const float* __restrict__ b3) {
    int n = blockIdx.x;
    int o = threadIdx.x;
    __shared__ float zs[64];
    zs[o] = g_z[n * 64 + o];
    __syncthreads();
    float acc = 0.f;
    #pragma unroll 8
    for (int i = 0; i < 64; i++) acc += zs[i] * b3[i * 64 + o];
    g_Bz[n * 64 + o] = acc;
}

// ============================================================================
// Edge-tile mma kernel: per tile (node n, 64 edges):
//   msg[64,64] = h2[rows,1024] @ T_n[64,1024]^T   (3-pass split mma)
//   agg[dst] += (msg + Bz[n]) * invcnt[dst]
// 256 threads = 8 warps (4m x 2n). BK=64, K=1024, double-sync 2-stage.
// half=0: tiles of nodes [0,512); half=1: tiles of nodes [512,961).
// ============================================================================
#define E2_LDA 72
#define E2_STAGE_BYTES (256 * E2_LDA * 2)   // 36864
#define E2_SMEM (2 * E2_STAGE_BYTES)        // 73728
#define E2_OFF_AL (64 * E2_LDA * 2)
#define E2_OFF_BH (128 * E2_LDA * 2)
#define E2_OFF_BL (192 * E2_LDA * 2)

__global__ void __launch_bounds__(256) edge_mma_kernel(int half) {
    const int tstart = half ? g_tileptr[HALF_NODES] : 0;
    const int tend   = half ? g_ntiles : g_tileptr[HALF_NODES];
    const int bid = tstart + blockIdx.x;
    if (bid >= tend) return;
    const int tm = g_tilemap[bid];
    const int n = tm & 0xFFFF;
    const int t = tm >> 16;
    const int base = g_srcptr[n];
    const int nE = g_srcptr[n + 1] - base;
    const int row0 = t * 64;

    extern __shared__ __align__(16) __half esm[];
    const uint32_t sbase = smem_u32(esm);

    const int tid  = threadIdx.x;
    const int lane = tid & 31;
    const int wid  = tid >> 5;
    const int wm   = wid & 3;        // 4 m-groups of 16 rows
    const int wn   = wid >> 2;       // 2 n-groups of 32 cols

    const int lrow = tid >> 2;
    const int lcol = (tid & 3) * 16;
    const int aslot = row0 + lrow;
    const int apred = (aslot < nE);
    const int asz = apred ? 16 : 0;
    const int e_a = apred ? g_eord[base + aslot] : 0;
    const __half* gAh = g_h2h + (size_t)e_a * KDIM + lcol;
    const __half* gAl = g_h2l + (size_t)e_a * KDIM + lcol;
    const __half* gBh = g_Th + (size_t)n * NT2 + lrow * KDIM + lcol;
    const __half* gBl = g_Tl + (size_t)n * NT2 + lrow * KDIM + lcol;
    const uint32_t sA = (lrow * E2_LDA + lcol) * 2;
    const uint32_t sB = ((lrow + 128) * E2_LDA + lcol) * 2;

    const uint32_t aoff = ((wm * 16 + (lane & 15)) * E2_LDA + ((lane >> 4) << 3)) * 2;
    uint32_t boff[2];
    #pragma unroll
    for (int tp = 0; tp < 2; tp++) {
        int r = 128 + wn * 32 + tp * 16 + ((lane >> 4) << 3) + (lane & 7);
        int c = ((lane >> 3) & 1) * 8;
        boff[tp] = (r * E2_LDA + c) * 2;
    }

    float acc[4][4];
    #pragma unroll
    for (int nt = 0; nt < 4; nt++)
        #pragma unroll
        for (int i = 0; i < 4; i++) acc[nt][i] = 0.f;

    #define E2_LOAD(st, kt) do { \
        uint32_t so = sbase + (st) * E2_STAGE_BYTES; \
        int ko = (kt) * 64; \
        cp_async16_pred(so + sA,      gAh + ko,     asz); \
        cp_async16_pred(so + sA + 16, gAh + ko + 8, asz); \
        cp_async16_pred(so + E2_OFF_AL + sA,      gAl + ko,     asz); \
        cp_async16_pred(so + E2_OFF_AL + sA + 16, gAl + ko + 8, asz); \
        cp_async16(so + sB,      gBh + ko); \
        cp_async16(so + sB + 16, gBh + ko + 8); \
        uint32_t sBl = sB + (E2_OFF_BL - E2_OFF_BH); \
        cp_async16(so + sBl,      gBl + ko); \
        cp_async16(so + sBl + 16, gBl + ko + 8); \
    } while (0)

    E2_LOAD(0, 0);
    cp_async_commit();

    for (int kt = 0; kt < 16; kt++) {
        if (kt + 1 < 16) {
            E2_LOAD((kt + 1) & 1, kt + 1);
            cp_async_commit();
            cp_async_wait<1>();
        } else {
            cp_async_wait<0>();
        }
        __syncthreads();

        const uint32_t sb = sbase + (kt & 1) * E2_STAGE_BYTES;
        #pragma unroll
        for (int kk = 0; kk < 4; kk++) {
            uint32_t ah[4], al[4];
            LDSM4(ah[0], ah[1], ah[2], ah[3], sb + aoff + kk * 32);
            LDSM4(al[0], al[1], al[2], al[3], sb + E2_OFF_AL + aoff + kk * 32);
            uint32_t bh[2][4], bl[2][4];
            #pragma unroll
            for (int tp = 0; tp < 2; tp++) {
                LDSM4(bh[tp][0], bh[tp][1], bh[tp][2], bh[tp][3],
                      sb + boff[tp] + kk * 32);
                LDSM4(bl[tp][0], bl[tp][1], bl[tp][2], bl[tp][3],
                      sb + (E2_OFF_BL - E2_OFF_BH) + boff[tp] + kk * 32);
            }
            #pragma unroll
            for (int nt = 0; nt < 4; nt++) {
                const uint32_t* bhp = bh[nt >> 1];
                const uint32_t* blp = bl[nt >> 1];
                uint32_t h0, h1, l0, l1;
                if (nt & 1) { h0 = bhp[2]; h1 = bhp[3]; l0 = blp[2]; l1 = blp[3]; }
                else        { h0 = bhp[0]; h1 = bhp[1]; l0 = blp[0]; l1 = blp[1]; }
                mma_16816(acc[nt], ah, h0, h1);
                mma_16816(acc[nt], ah, l0, l1);
                mma_16816(acc[nt], al, h0, h1);
            }
        }
        __syncthreads();
    }
    #undef E2_LOAD

    const int r1 = wm * 16 + (lane >> 2);
    const int r2 = r1 + 8;
    const int s1 = row0 + r1;
    const int s2 = row0 + r2;
    int e1 = -1, e2 = -1;
    float ic1 = 0.f, ic2 = 0.f;
    int d1 = 0, d2 = 0;
    if (s1 < nE) { e1 = g_eord[base + s1]; d1 = g_dst[e1]; ic1 = g_invcnt[d1]; }
    if (s2 < nE) { e2 = g_eord[base + s2]; d2 = g_dst[e2]; ic2 = g_invcnt[d2]; }

    #pragma unroll
    for (int nt = 0; nt < 4; nt++) {
        int col = wn * 32 + nt * 8 + (lane & 3) * 2;
        float bz0 = g_Bz[n * 64 + col];
        float bz1 = g_Bz[n * 64 + col + 1];
        if (e1 >= 0) {
            atomicAdd(g_agg + d1 * 64 + col,     (acc[nt][0] + bz0) * ic1);
            atomicAdd(g_agg + d1 * 64 + col + 1, (acc[nt][1] + bz1) * ic1);
        }
        if (e2 >= 0) {
            atomicAdd(g_agg + d2 * 64 + col,     (acc[nt][2] + bz0) * ic2);
            atomicAdd(g_agg + d2 * 64 + col + 1, (acc[nt][3] + bz1) * ic2);
        }
    }
}

// Fused: z = relu(agg + z@root + conv_b); agg=0; write zp hi/lo + Bz for next iter.
__global__ void update_fused_kernel(const float* __restrict__ root,
                                    const float* __restrict__ convb,
                                    const float* __restrict__ b3) {
    int n = blockIdx.x;
    int j = threadIdx.x;
    __shared__ float zr[64], zn[64];
    zr[j] = g_z[n * 64 + j];
    __syncthreads();
    float acc = g_agg[n * 64 + j] + convb[j];
    #pragma unroll 8
    for (int k = 0; k < 64; k++) acc += zr[k] * root[k * 64 + j];
    float z = fmaxf(acc, 0.f);
    g_z[n * 64 + j] = z;
    g_agg[n * 64 + j] = 0.f;
    __half hi = __float2half_rn(z);
    g_zph[n * 64 + j] = hi;
    g_zpl[n * 64 + j] = __float2half_rn(z - __half2float(hi));
    zn[j] = z;
    __syncthreads();
    float b = 0.f;
    #pragma unroll 8
    for (int i = 0; i < 64; i++) b += zn[i] * b3[i * 64 + j];
    g_Bz[n * 64 + j] = b;
}

// out = z @ fc2_w + fc2_b  (one warp per node)
__global__ void final_kernel(const float* __restrict__ fc2w,
                             const float* __restrict__ fc2b,
                             float* __restrict__ out) {
    int w = threadIdx.x >> 5;
    int lane = threadIdx.x & 31;
    int n = blockIdx.x * 4 + w;
    if (n >= N_NODES) return;
    float v = g_z[n * 64 + lane] * fc2w[lane]
            + g_z[n * 64 + lane + 32] * fc2w[lane + 32];
    #pragma unroll
    for (int o = 16; o; o >>= 1) v += __shfl_xor_sync(0xffffffffu, v, o);
    if (lane == 0) out[n] = v + fc2b[0];
}

// ============================================================================
// Launch — prologue fork/join + per-depth half-split pipelining:
//   TG(H1) on s1 runs concurrent with TG(H0)+edge_mma(H0) on main.
// ============================================================================
extern "C" void kernel_launch(void* const* d_in, const int* in_sizes, int n_in,
                              void* d_out, int out_size) {
    const float* x     = (const float*)d_in[0];
    const void*  ei    = d_in[1];
    const float* attr  = (const float*)d_in[2];
    const float* fc1w  = (const float*)d_in[3];
    const float* fc1b  = (const float*)d_in[4];
    const float* kw1   = (const float*)d_in[5];
    const float* kb1   = (const float*)d_in[6];
    const float* kw2   = (const float*)d_in[7];
    const float* kb2   = (const float*)d_in[8];
    const float* kw3   = (const float*)d_in[9];
    const float* kb3   = (const float*)d_in[10];
    const float* root  = (const float*)d_in[11];
    const float* convb = (const float*)d_in[12];
    const float* fc2w  = (const float*)d_in[13];
    const float* fc2b  = (const float*)d_in[14];
    float* out = (float*)d_out;
    (void)in_sizes; (void)n_in; (void)out_size;

    static int init_done = 0;
    static __half *h1h, *h1l, *h2h, *h2l, *w2th, *w2tl, *k3th, *k3tl,
                  *zph, *zpl, *Th, *Tl;
    static cudaStream_t s1;
    static cudaEvent_t evFork, evJoin, evM, evB;
    if (!init_done) {
        cudaFuncSetAttribute(gemm_split_kernel<true>,
                             cudaFuncAttributeMaxDynamicSharedMemorySize,
                             GEMM_DSMEM);
        cudaFuncSetAttribute(gemm_split_kernel<false>,
                             cudaFuncAttributeMaxDynamicSharedMemorySize,
                             GEMM_DSMEM);
        cudaFuncSetAttribute(edge_mma_kernel,
                             cudaFuncAttributeMaxDynamicSharedMemorySize,
                             E2_SMEM);
        cudaGetSymbolAddress((void**)&h1h,  g_h1h);
        cudaGetSymbolAddress((void**)&h1l,  g_h1l);
        cudaGetSymbolAddress((void**)&h2h,  g_h2h);
        cudaGetSymbolAddress((void**)&h2l,  g_h2l);
        cudaGetSymbolAddress((void**)&w2th, g_w2th);
        cudaGetSymbolAddress((void**)&w2tl, g_w2tl);
        cudaGetSymbolAddress((void**)&k3th, g_k3th);
        cudaGetSymbolAddress((void**)&k3tl, g_k3tl);
        cudaGetSymbolAddress((void**)&zph,  g_zph);
        cudaGetSymbolAddress((void**)&zpl,  g_zpl);
        cudaGetSymbolAddress((void**)&Th,   g_Th);
        cudaGetSymbolAddress((void**)&Tl,   g_Tl);
        cudaStreamCreateWithFlags(&s1, cudaStreamNonBlocking);
        cudaEventCreateWithFlags(&evFork, cudaEventDisableTiming);
        cudaEventCreateWithFlags(&evJoin, cudaEventDisableTiming);
        cudaEventCreateWithFlags(&evM, cudaEventDisableTiming);
        cudaEventCreateWithFlags(&evB, cudaEventDisableTiming);
        init_done = 1;
    }

    // ---- prologue fork: setup on s1, h2 production on main ----
    cudaEventRecord(evFork, 0);
    cudaStreamWaitEvent(s1, evFork, 0);

    l1_kernel<<<N_EDGES, 256>>>(attr, kw1, kb1);
    cast_w2_kernel<<<(KDIM * KDIM + 255) / 256, 256>>>(kw2);
    gemm_split_kernel<true><<<dim3(KDIM / BN, N_EDGES / BM), 256, GEMM_DSMEM>>>(
        h1h, h1l, w2th, w2tl, h2h, h2l, kb2, KDIM, KDIM, 1);

    detect_kernel<<<1, 32, 0, s1>>>(ei);
    zero_z0_kernel<<<(N_NODES * WIDTH + 255) / 256, 256, 0, s1>>>(x, fc1w, fc1b);
    decode_count_kernel<<<N_EDGES / 256, 256, 0, s1>>>(ei);
    scan_kernel<<<1, 1024, 0, s1>>>();
    scatter_kernel<<<N_EDGES / 256, 256, 0, s1>>>();
    tilefill_kernel<<<N_NODES, 32, 0, s1>>>();
    k3tt2_kernel<<<(NT2 * WIDTH + 255) / 256, 256, 0, s1>>>(kw3);
    zsplit_kernel<<<(MPAD * WIDTH + 255) / 256, 256, 0, s1>>>();
    bz_kernel<<<N_NODES, 64, 0, s1>>>(kb3);
    cudaEventRecord(evJoin, s1);
    cudaStreamWaitEvent(0, evJoin, 0);

    // ---- depth loop with half-split pipelining ----
    const dim3 tg_half(NT2 / BN, HALF_NODES / BM);   // 512 rows per half
    const size_t h1off = (size_t)HALF_NODES * WIDTH; // zp row offset
    const size_t t1off = (size_t)HALF_NODES * NT2;   // T row offset

    for (int d = 0; d < 6; d++) {
        // fork: TG(H1) on s1
        cudaEventRecord(evM, 0);
        cudaStreamWaitEvent(s1, evM, 0);
        gemm_split_kernel<false><<<tg_half, 256, GEMM_DSMEM, s1>>>(
            zph + h1off, zpl + h1off, k3th, k3tl,
            Th + t1off, Tl + t1off, nullptr, NT2, WIDTH, 0);
        cudaEventRecord(evB, s1);

        // main: TG(H0) then edge_mma(H0) — overlaps TG(H1)
        gemm_split_kernel<false><<<tg_half, 256, GEMM_DSMEM>>>(
            zph, zpl, k3th, k3tl, Th, Tl, nullptr, NT2, WIDTH, 0);
        edge_mma_kernel<<<MAX_TILES, 256, E2_SMEM>>>(0);

        // join, then edge_mma(H1) and update
        cudaStreamWaitEvent(0, evB, 0);
        edge_mma_kernel<<<MAX_TILES, 256, E2_SMEM>>>(1);
        update_fused_kernel<<<N_NODES, 64>>>(root, convb, kb3);
    }

    final_kernel<<<(N_NODES + 3) / 4, 128>>>(fc2w, fc2b, out);
}

// round 15
// speedup vs baseline: 1.0595x; 1.0595x over previous
#include <cuda_runtime.h>
#include <cuda_fp16.h>
#include <cstdint>

// ============================================================================
// Problem constants
// ============================================================================
#define N_NODES 961
#define N_EDGES 32768
#define WIDTH   64
#define KDIM    1024
#define N3      4096   // WIDTH*WIDTH
#define MPAD    1024   // padded node count for T-GEMM
#define NT2     65536  // 64*1024 (o,j) pairs
#define MAX_TILES 1473 // <= N_NODES + N_EDGES/64

// ============================================================================
// Device scratch (sanctioned: __device__ globals, no runtime allocation)
// ============================================================================
__device__ __half g_h1h[(size_t)N_EDGES * KDIM];         //  64 MB
__device__ __half g_h1l[(size_t)N_EDGES * KDIM];         //  64 MB
__device__ __half g_h2h[(size_t)N_EDGES * KDIM];         //  64 MB
__device__ __half g_h2l[(size_t)N_EDGES * KDIM];         //  64 MB
__device__ __half g_Th [(size_t)MPAD * NT2];             // 128 MB  T[n][o][j] hi
__device__ __half g_Tl [(size_t)MPAD * NT2];             // 128 MB  T[n][o][j] lo
__device__ __half g_w2th[(size_t)KDIM * KDIM];           //   2 MB
__device__ __half g_w2tl[(size_t)KDIM * KDIM];           //   2 MB
__device__ __half g_k3th[(size_t)NT2 * WIDTH];           //   8 MB  k3tt2 hi
__device__ __half g_k3tl[(size_t)NT2 * WIDTH];           //   8 MB
__device__ __half g_zph[MPAD * WIDTH];
__device__ __half g_zpl[MPAD * WIDTH];
__device__ float  g_Bz [N_NODES * WIDTH];
__device__ float  g_z  [N_NODES * WIDTH];
__device__ float  g_agg[N_NODES * WIDTH];
__device__ float  g_cnt[N_NODES];
__device__ float  g_invcnt[N_NODES];
__device__ int    g_src[N_EDGES];
__device__ int    g_dst[N_EDGES];
__device__ int    g_srccnt[N_NODES];
__device__ int    g_scur[N_NODES];
__device__ int    g_srcptr[N_NODES + 1];
__device__ int    g_tileptr[N_NODES + 1];
__device__ int    g_eord[N_EDGES];
__device__ int    g_tilemap[MAX_TILES];
__device__ int    g_ntiles;
__device__ int    g_flag;

// ============================================================================
// PTX helpers (compute_100-safe: cp.async / ldmatrix / mma.sync only)
// ============================================================================
__device__ __forceinline__ uint32_t smem_u32(const void* smem_ptr) {
    uint32_t addr;
    asm("{ .reg .u64 tmp; cvta.to.shared.u64 tmp, %1; cvt.u32.u64 %0, tmp; }"
        : "=r"(addr) : "l"(smem_ptr));
    return addr;
}

__device__ __forceinline__ void cp_async16(uint32_t saddr, const void* gaddr) {
    asm volatile("cp.async.cg.shared.global [%0], [%1], 16;\n"
                 :: "r"(saddr), "l"(gaddr));
}
// Predicated: src_size=0 -> zero-fill the 16B destination.
__device__ __forceinline__ void cp_async16_pred(uint32_t saddr, const void* gaddr,
                                                int src_size) {
    asm volatile("cp.async.cg.shared.global [%0], [%1], 16, %2;\n"
                 :: "r"(saddr), "l"(gaddr), "r"(src_size));
}
__device__ __forceinline__ void cp_async_commit() {
    asm volatile("cp.async.commit_group;\n" ::: "memory");
}
template <int N>
__device__ __forceinline__ void cp_async_wait() {
    asm volatile("cp.async.wait_group %0;\n" :: "n"(N) : "memory");
}

#define LDSM4(r0, r1, r2, r3, addr) \
    asm volatile("ldmatrix.sync.aligned.m8n8.x4.shared.b16 {%0,%1,%2,%3}, [%4];" \
                 : "=r"(r0), "=r"(r1), "=r"(r2), "=r"(r3) : "r"(addr))

__device__ __forceinline__ void mma_16816(float* c, const uint32_t* a,
                                          uint32_t b0, uint32_t b1) {
    asm volatile(
        "mma.sync.aligned.m16n8k16.row.col.f32.f16.f16.f32 "
        "{%0,%1,%2,%3}, {%4,%5,%6,%7}, {%8,%9}, {%0,%1,%2,%3};"
        : "+f"(c[0]), "+f"(c[1]), "+f"(c[2]), "+f"(c[3])
        : "r"(a[0]), "r"(a[1]), "r"(a[2]), "r"(a[3]), "r"(b0), "r"(b1));
}

// ============================================================================
// Setup kernels
// ============================================================================

// h1 = relu(edge_attr @ k_w1 + b1), split hi/lo fp16 out
__global__ void l1_kernel(const float* __restrict__ attr,
                          const float* __restrict__ w1,
                          const float* __restrict__ b1) {
    int e = blockIdx.x;
    __shared__ float a[6];
    if (threadIdx.x < 6) a[threadIdx.x] = attr[e * 6 + threadIdx.x];
    __syncthreads();
    for (int j = threadIdx.x; j < KDIM; j += blockDim.x) {
        float acc = b1[j];
        #pragma unroll
        for (int i = 0; i < 6; i++) acc += a[i] * w1[i * KDIM + j];
        acc = fmaxf(acc, 0.f);
        __half hi = __float2half_rn(acc);
        g_h1h[(size_t)e * KDIM + j] = hi;
        g_h1l[(size_t)e * KDIM + j] = __float2half_rn(acc - __half2float(hi));
    }
}

// Detect whether edge_index buffer is int64 or int32.
__global__ void detect_kernel(const void* ei) {
    if (threadIdx.x == 0 && blockIdx.x == 0) {
        const long long* p = (const long long*)ei;
        int ok = 1;
        for (int i = 0; i < 64; i++) {
            long long v = p[i];
            if (v < 0 || v >= N_NODES) { ok = 0; break; }
        }
        g_flag = ok;   // 1 => int64, 0 => int32
    }
}

// w2t hi/lo: dst[n*1024 + k] = split( kw2[k*1024 + n] )
__global__ void cast_w2_kernel(const float* __restrict__ src) {
    int i = blockIdx.x * blockDim.x + threadIdx.x;
    if (i >= KDIM * KDIM) return;
    int n = i >> 10;
    int k = i & 1023;
    float v = src[k * KDIM + n];
    __half hi = __float2half_rn(v);
    g_w2th[i] = hi;
    g_w2tl[i] = __float2half_rn(v - __half2float(hi));
}

// Zero counters + compute z0 = x@fc1 + b.
__global__ void zero_z0_kernel(const float* __restrict__ x,
                               const float* __restrict__ w,
                               const float* __restrict__ b) {
    int i = blockIdx.x * blockDim.x + threadIdx.x;
    if (i < N_NODES) {
        g_cnt[i] = 0.f;
        g_srccnt[i] = 0;
        g_scur[i] = 0;
    }
    if (i < N_NODES * WIDTH) {
        int n = i >> 6, j = i & 63;
        g_agg[i] = 0.f;
        g_z[i] = x[n] * w[j] + b[j];
    }
}

// k3tt2 hi/lo (o-major): row r2 = o*1024 + j, col i:
//   k3tt2[r2*64 + i] = kw3[j*4096 + i*64 + o]
__global__ void k3tt2_kernel(const float* __restrict__ kw3) {
    int idx = blockIdx.x * blockDim.x + threadIdx.x;  // < 65536*64
    int r2 = idx >> 6;
    int i = idx & 63;
    int o = r2 >> 10;
    int j = r2 & 1023;
    float v = kw3[(size_t)j * N3 + i * 64 + o];
    __half hi = __float2half_rn(v);
    g_k3th[idx] = hi;
    g_k3tl[idx] = __float2half_rn(v - __half2float(hi));
}

// Decode edge_index, count dst (for mean) and src (for CSR).
__global__ void decode_count_kernel(const void* ei) {
    int e = blockIdx.x * blockDim.x + threadIdx.x;
    if (e >= N_EDGES) return;
    int s, d;
    if (g_flag) {
        const long long* p = (const long long*)ei;
        s = (int)p[e];
        d = (int)p[N_EDGES + e];
    } else {
        const int* p = (const int*)ei;
        s = p[e];
        d = p[N_EDGES + e];
    }
    g_src[e] = s;
    g_dst[e] = d;
    atomicAdd(&g_cnt[d], 1.0f);
    atomicAdd(&g_srccnt[s], 1);
}

// Scans: srccnt -> srcptr (exclusive), invcnt; 64-edge tile counts -> tileptr.
__global__ void scan_kernel() {
    __shared__ int s[1024];
    int tid = threadIdx.x;
    int v = (tid < N_NODES) ? g_srccnt[tid] : 0;
    s[tid] = v;
    __syncthreads();
    #pragma unroll
    for (int off = 1; off < 1024; off <<= 1) {
        int t = (tid >= off) ? s[tid - off] : 0;
        __syncthreads();
        s[tid] += t;
        __syncthreads();
    }
    if (tid < N_NODES) {
        g_srcptr[tid] = s[tid] - v;
        g_invcnt[tid] = 1.0f / fmaxf(g_cnt[tid], 1.0f);
    }
    if (tid == 0) g_srcptr[N_NODES] = N_EDGES;
    __syncthreads();

    int tc = (tid < N_NODES) ? ((v + 63) >> 6) : 0;
    s[tid] = tc;
    __syncthreads();
    #pragma unroll
    for (int off = 1; off < 1024; off <<= 1) {
        int t = (tid >= off) ? s[tid - off] : 0;
        __syncthreads();
        s[tid] += t;
        __syncthreads();
    }
    if (tid < N_NODES) g_tileptr[tid] = s[tid] - tc;
    if (tid == 1023) {
        g_tileptr[N_NODES] = s[1023];
        g_ntiles = s[1023];
    }
}

// Scatter edges into src-sorted order; fill tile map.
__global__ void scatter_kernel() {
    int e = blockIdx.x * blockDim.x + threadIdx.x;
    if (e >= N_EDGES) return;
    int s = g_src[e];
    int pos = g_srcptr[s] + atomicAdd(&g_scur[s], 1);
    g_eord[pos] = e;
}
__global__ void tilefill_kernel() {
    int n = blockIdx.x;
    int tp = g_tileptr[n];
    int tc = g_tileptr[n + 1] - tp;
    for (int t = threadIdx.x; t < tc; t += blockDim.x)
        g_tilemap[tp + t] = n | (t << 16);
}

// ============================================================================
// Split-fp16 3-pass GEMM:  C(hi,lo) = act(A @ BT^T [+ bias])
//   C = A_hi*B_hi + A_hi*B_lo + A_lo*B_hi  (fp32 accum), out split to fp16 pair
// CTA tile 128x128xBK32, 2-stage cp.async, 256 threads (4m x 2n).
// SINGLE_SYNC=true : single-barrier loop (best for 2-CTA/SM GEMM1 regime)
// SINGLE_SYNC=false: classic double-barrier loop (best for many-wave T-GEMM)
// ============================================================================
#define BM 128
#define BN 128
#define BK 32
#define LDA 40
#define STAGE_HALFS (512 * LDA)
#define STAGE_BYTES (STAGE_HALFS * 2) // 40960
#define GEMM_DSMEM (2 * STAGE_BYTES)  // 81920

#define OFF_AL (128 * LDA * 2)
#define OFF_BH (256 * LDA * 2)
#define OFF_BL (384 * LDA * 2)

template <bool SINGLE_SYNC>
__global__ void __launch_bounds__(256) gemm_split_kernel(
        const __half* __restrict__ Ah, const __half* __restrict__ Al,
        const __half* __restrict__ Bh, const __half* __restrict__ Bl,
        __half* __restrict__ Ch, __half* __restrict__ Cl,
        const float* __restrict__ bias, int N, int K, int relu) {
    extern __shared__ __align__(16) __half sm[];

    const int tid  = threadIdx.x;
    const int lane = tid & 31;
    const int wid  = tid >> 5;
    const int wm   = wid & 3;
    const int wn   = wid >> 2;
    const int bn   = blockIdx.x;
    const int bm   = blockIdx.y;

    const uint32_t sbase = smem_u32(sm);

    const int crow = tid >> 2;
    const int ccol = (tid & 3) * 8;
    const size_t arow = (size_t)(bm * BM + crow) * K + ccol;
    const __half* gAh0 = Ah + arow;
    const __half* gAh1 = gAh0 + (size_t)64 * K;
    const __half* gAl0 = Al + arow;
    const __half* gAl1 = gAl0 + (size_t)64 * K;
    const size_t brow = (size_t)(bn * BN + crow) * K + ccol;
    const __half* gBh0 = Bh + brow;
    const __half* gBh1 = gBh0 + (size_t)64 * K;
    const __half* gBl0 = Bl + brow;
    const __half* gBl1 = gBl0 + (size_t)64 * K;
    uint32_t so_[8];
    #pragma unroll
    for (int r = 0; r < 8; r++)
        so_[r] = ((crow + r * 64) * LDA + ccol) * 2;

    uint32_t aoff[2];
    #pragma unroll
    for (int mt = 0; mt < 2; mt++) {
        int r = wm * 32 + mt * 16 + (lane & 15);
        int c = (lane >> 4) << 3;
        aoff[mt] = (r * LDA + c) * 2;
    }
    uint32_t boff[4];
    #pragma unroll
    for (int tp = 0; tp < 4; tp++) {
        int r = wn * 64 + tp * 16 + ((lane >> 4) << 3) + (lane & 7);
        int c = ((lane >> 3) & 1) * 8;
        boff[tp] = OFF_BH + (r * LDA + c) * 2;
    }

    float acc[2][8][4];
    #pragma unroll
    for (int mt = 0; mt < 2; mt++)
        #pragma unroll
        for (int nt = 0; nt < 8; nt++)
            #pragma unroll
            for (int i = 0; i < 4; i++) acc[mt][nt][i] = 0.f;

    const int nkt = K / BK;

    #define G_LOAD(st, kt) do { \
        uint32_t so = sbase + (st) * STAGE_BYTES; \
        int go = (kt) * BK; \
        cp_async16(so + so_[0], gAh0 + go); \
        cp_async16(so + so_[1], gAh1 + go); \
        cp_async16(so + so_[2], gAl0 + go); \
        cp_async16(so + so_[3], gAl1 + go); \
        cp_async16(so + so_[4], gBh0 + go); \
        cp_async16(so + so_[5], gBh1 + go); \
        cp_async16(so + so_[6], gBl0 + go); \
        cp_async16(so + so_[7], gBl1 + go); \
    } while (0)

    G_LOAD(0, 0);
    cp_async_commit();

    for (int kt = 0; kt < nkt; kt++) {
        if (SINGLE_SYNC) {
            cp_async_wait<0>();
            __syncthreads();
            if (kt + 1 < nkt) {
                G_LOAD((kt + 1) & 1, kt + 1);
                cp_async_commit();
            }
        } else {
            if (kt + 1 < nkt) {
                G_LOAD((kt + 1) & 1, kt + 1);
                cp_async_commit();
                cp_async_wait<1>();
            } else {
                cp_async_wait<0>();
            }
            __syncthreads();
        }

        const uint32_t sb = sbase + (kt & 1) * STAGE_BYTES;
        #pragma unroll
        for (int kk = 0; kk < 2; kk++) {
            uint32_t ah[2][4], al[2][4];
            #pragma unroll
            for (int mt = 0; mt < 2; mt++) {
                LDSM4(ah[mt][0], ah[mt][1], ah[mt][2], ah[mt][3],
                      sb + aoff[mt] + kk * 32);
                LDSM4(al[mt][0], al[mt][1], al[mt][2], al[mt][3],
                      sb + OFF_AL + aoff[mt] + kk * 32);
            }
            uint32_t bh[4][4], bl[4][4];
            #pragma unroll
            for (int tp = 0; tp < 4; tp++) {
                LDSM4(bh[tp][0], bh[tp][1], bh[tp][2], bh[tp][3],
                      sb + boff[tp] + kk * 32);
                LDSM4(bl[tp][0], bl[tp][1], bl[tp][2], bl[tp][3],
                      sb + (OFF_BL - OFF_BH) + boff[tp] + kk * 32);
            }
            #pragma unroll
            for (int mt = 0; mt < 2; mt++)
                #pragma unroll
                for (int nt = 0; nt < 8; nt++) {
                    const uint32_t* bhp = bh[nt >> 1];
                    const uint32_t* blp = bl[nt >> 1];
                    uint32_t h0, h1, l0, l1;
                    if (nt & 1) { h0 = bhp[2]; h1 = bhp[3]; l0 = blp[2]; l1 = blp[3]; }
                    else        { h0 = bhp[0]; h1 = bhp[1]; l0 = blp[0]; l1 = blp[1]; }
                    mma_16816(acc[mt][nt], ah[mt], h0, h1);
                    mma_16816(acc[mt][nt], ah[mt], l0, l1);
                    mma_16816(acc[mt][nt], al[mt], h0, h1);
                }
        }
        if (!SINGLE_SYNC) __syncthreads();
    }
    #undef G_LOAD

    #pragma unroll
    for (int mt = 0; mt < 2; mt++) {
        int r0 = bm * BM + wm * 32 + mt * 16 + (lane >> 2);
        #pragma unroll
        for (int nt = 0; nt < 8; nt++) {
            int col = bn * BN + wn * 64 + nt * 8 + (lane & 3) * 2;
            float b0 = 0.f, b1 = 0.f;
            if (bias) { b0 = __ldg(bias + col); b1 = __ldg(bias + col + 1); }
            float v[4];
            v[0] = acc[mt][nt][0] + b0;
            v[1] = acc[mt][nt][1] + b1;
            v[2] = acc[mt][nt][2] + b0;
            v[3] = acc[mt][nt][3] + b1;
            if (relu) {
                v[0] = fmaxf(v[0], 0.f); v[1] = fmaxf(v[1], 0.f);
                v[2] = fmaxf(v[2], 0.f); v[3] = fmaxf(v[3], 0.f);
            }
            __half h0 = __float2half_rn(v[0]), h1 = __float2half_rn(v[1]);
            __half h2v = __float2half_rn(v[2]), h3 = __float2half_rn(v[3]);
            size_t o0 = (size_t)r0 * N + col;
            size_t o1 = (size_t)(r0 + 8) * N + col;
            *(__half2*)(Ch + o0) = __halves2half2(h0, h1);
            *(__half2*)(Ch + o1) = __halves2half2(h2v, h3);
            *(__half2*)(Cl + o0) = __halves2half2(
                __float2half_rn(v[0] - __half2float(h0)),
                __float2half_rn(v[1] - __half2float(h1)));
            *(__half2*)(Cl + o1) = __halves2half2(
                __float2half_rn(v[2] - __half2float(h2v)),
                __float2half_rn(v[3] - __half2float(h3)));
        }
    }
}

// ============================================================================
// Depth-loop kernels
// ============================================================================

// Split z into padded hi/lo fp16 (rows >= N_NODES -> 0). Initial use only.
__global__ void zsplit_kernel() {
    int i = blockIdx.x * blockDim.x + threadIdx.x;
    if (i >= MPAD * WIDTH) return;
    int n = i >> 6;
    float v = (n < N_NODES) ? g_z[i] : 0.f;
    __half hi = __float2half_rn(v);
    g_zph[i] = hi;
    g_zpl[i] = __float2half_rn(v - __half2float(hi));
}

// Bz[n,o] = sum_i z[n,i] * b3[i*64+o]. Initial use only.
__global__ void bz_kernel(const float* __restrict__ b3) {
    int n = blockIdx.x;
    int o = threadIdx.x;
    __shared__ float zs[64];
    zs[o] = g_z[n * 64 + o];
    __syncthreads();
    float acc = 0.f;
    #pragma unroll 8
    for (int i = 0; i < 64; i++) acc += zs[i] * b3[i * 64 + o];
    g_Bz[n * 64 + o] = acc;
}

// ============================================================================
// Edge-tile mma kernel: per tile (node n, 64 edges):
//   msg[64,64] = h2[rows,1024] @ T_n[64,1024]^T   (3-pass split mma)
//   agg[dst] += (msg + Bz[n]) * invcnt[dst]
// 256 threads = 8 warps (4m x 2n). BK=64, K=1024, double-sync 2-stage.
// smem rows (LDA=72): Ahi 0-63, Alo 64-127, Bhi 128-191, Blo 192-255
// ============================================================================
#define E2_LDA 72
#define E2_STAGE_BYTES (256 * E2_LDA * 2)   // 36864
#define E2_SMEM (2 * E2_STAGE_BYTES)        // 73728
#define E2_OFF_AL (64 * E2_LDA * 2)
#define E2_OFF_BH (128 * E2_LDA * 2)
#define E2_OFF_BL (192 * E2_LDA * 2)

__global__ void __launch_bounds__(256) edge_mma_kernel() {
    const int bid = blockIdx.x;
    if (bid >= g_ntiles) return;
    const int tm = g_tilemap[bid];
    const int n = tm & 0xFFFF;
    const int t = tm >> 16;
    const int base = g_srcptr[n];
    const int nE = g_srcptr[n + 1] - base;
    const int row0 = t * 64;

    extern __shared__ __align__(16) __half esm[];
    const uint32_t sbase = smem_u32(esm);

    const int tid  = threadIdx.x;
    const int lane = tid & 31;
    const int wid  = tid >> 5;
    const int wm   = wid & 3;        // 4 m-groups of 16 rows
    const int wn   = wid >> 2;       // 2 n-groups of 32 cols

    const int lrow = tid >> 2;
    const int lcol = (tid & 3) * 16;
    const int aslot = row0 + lrow;
    const int apred = (aslot < nE);
    const int asz = apred ? 16 : 0;
    const int e_a = apred ? g_eord[base + aslot] : 0;
    const __half* gAh = g_h2h + (size_t)e_a * KDIM + lcol;
    const __half* gAl = g_h2l + (size_t)e_a * KDIM + lcol;
    const __half* gBh = g_Th + (size_t)n * NT2 + lrow * KDIM + lcol;
    const __half* gBl = g_Tl + (size_t)n * NT2 + lrow * KDIM + lcol;
    const uint32_t sA = (lrow * E2_LDA + lcol) * 2;
    const uint32_t sB = ((lrow + 128) * E2_LDA + lcol) * 2;

    const uint32_t aoff = ((wm * 16 + (lane & 15)) * E2_LDA + ((lane >> 4) << 3)) * 2;
    uint32_t boff[2];
    #pragma unroll
    for (int tp = 0; tp < 2; tp++) {
        int r = 128 + wn * 32 + tp * 16 + ((lane >> 4) << 3) + (lane & 7);
        int c = ((lane >> 3) & 1) * 8;
        boff[tp] = (r * E2_LDA + c) * 2;
    }

    float acc[4][4];
    #pragma unroll
    for (int nt = 0; nt < 4; nt++)
        #pragma unroll
        for (int i = 0; i < 4; i++) acc[nt][i] = 0.f;

    #define E2_LOAD(st, kt) do { \
        uint32_t so = sbase + (st) * E2_STAGE_BYTES; \
        int ko = (kt) * 64; \
        cp_async16_pred(so + sA,      gAh + ko,     asz); \
        cp_async16_pred(so + sA + 16, gAh + ko + 8, asz); \
        cp_async16_pred(so + E2_OFF_AL + sA,      gAl + ko,     asz); \
        cp_async16_pred(so + E2_OFF_AL + sA + 16, gAl + ko + 8, asz); \
        cp_async16(so + sB,      gBh + ko); \
        cp_async16(so + sB + 16, gBh + ko + 8); \
        uint32_t sBl = sB + (E2_OFF_BL - E2_OFF_BH); \
        cp_async16(so + sBl,      gBl + ko); \
        cp_async16(so + sBl + 16, gBl + ko + 8); \
    } while (0)

    E2_LOAD(0, 0);
    cp_async_commit();

    for (int kt = 0; kt < 16; kt++) {
        if (kt + 1 < 16) {
            E2_LOAD((kt + 1) & 1, kt + 1);
            cp_async_commit();
            cp_async_wait<1>();
        } else {
            cp_async_wait<0>();
        }
        __syncthreads();

        const uint32_t sb = sbase + (kt & 1) * E2_STAGE_BYTES;
        #pragma unroll
        for (int kk = 0; kk < 4; kk++) {
            uint32_t ah[4], al[4];
            LDSM4(ah[0], ah[1], ah[2], ah[3], sb + aoff + kk * 32);
            LDSM4(al[0], al[1], al[2], al[3], sb + E2_OFF_AL + aoff + kk * 32);
            uint32_t bh[2][4], bl[2][4];
            #pragma unroll
            for (int tp = 0; tp < 2; tp++) {
                LDSM4(bh[tp][0], bh[tp][1], bh[tp][2], bh[tp][3],
                      sb + boff[tp] + kk * 32);
                LDSM4(bl[tp][0], bl[tp][1], bl[tp][2], bl[tp][3],
                      sb + (E2_OFF_BL - E2_OFF_BH) + boff[tp] + kk * 32);
            }
            #pragma unroll
            for (int nt = 0; nt < 4; nt++) {
                const uint32_t* bhp = bh[nt >> 1];
                const uint32_t* blp = bl[nt >> 1];
                uint32_t h0, h1, l0, l1;
                if (nt & 1) { h0 = bhp[2]; h1 = bhp[3]; l0 = blp[2]; l1 = blp[3]; }
                else        { h0 = bhp[0]; h1 = bhp[1]; l0 = blp[0]; l1 = blp[1]; }
                mma_16816(acc[nt], ah, h0, h1);
                mma_16816(acc[nt], ah, l0, l1);
                mma_16816(acc[nt], al, h0, h1);
            }
        }
        __syncthreads();
    }
    #undef E2_LOAD

    const int r1 = wm * 16 + (lane >> 2);
    const int r2 = r1 + 8;
    const int s1 = row0 + r1;
    const int s2 = row0 + r2;
    int e1 = -1, e2 = -1;
    float ic1 = 0.f, ic2 = 0.f;
    int d1 = 0, d2 = 0;
    if (s1 < nE) { e1 = g_eord[base + s1]; d1 = g_dst[e1]; ic1 = g_invcnt[d1]; }
    if (s2 < nE) { e2 = g_eord[base + s2]; d2 = g_dst[e2]; ic2 = g_invcnt[d2]; }

    #pragma unroll
    for (int nt = 0; nt < 4; nt++) {
        int col = wn * 32 + nt * 8 + (lane & 3) * 2;
        float bz0 = g_Bz[n * 64 + col];
        float bz1 = g_Bz[n * 64 + col + 1];
        if (e1 >= 0) {
            atomicAdd(g_agg + d1 * 64 + col,     (acc[nt][0] + bz0) * ic1);
            atomicAdd(g_agg + d1 * 64 + col + 1, (acc[nt][1] + bz1) * ic1);
        }
        if (e2 >= 0) {
            atomicAdd(g_agg + d2 * 64 + col,     (acc[nt][2] + bz0) * ic2);
            atomicAdd(g_agg + d2 * 64 + col + 1, (acc[nt][3] + bz1) * ic2);
        }
    }
}

// Fused: z = relu(agg + z@root + conv_b); agg=0; write zp hi/lo + Bz for next iter.
__global__ void update_fused_kernel(const float* __restrict__ root,
                                    const float* __restrict__ convb,
                                    const float* __restrict__ b3) {
    int n = blockIdx.x;
    int j = threadIdx.x;
    __shared__ float zr[64], zn[64];
    zr[j] = g_z[n * 64 + j];
    __syncthreads();
    float acc = g_agg[n * 64 + j] + convb[j];
    #pragma unroll 8
    for (int k = 0; k < 64; k++) acc += zr[k] * root[k * 64 + j];
    float z = fmaxf(acc, 0.f);
    g_z[n * 64 + j] = z;
    g_agg[n * 64 + j] = 0.f;
    __half hi = __float2half_rn(z);
    g_zph[n * 64 + j] = hi;
    g_zpl[n * 64 + j] = __float2half_rn(z - __half2float(hi));
    zn[j] = z;
    __syncthreads();
    float b = 0.f;
    #pragma unroll 8
    for (int i = 0; i < 64; i++) b += zn[i] * b3[i * 64 + j];
    g_Bz[n * 64 + j] = b;
}

// out = z @ fc2_w + fc2_b  (one warp per node)
__global__ void final_kernel(const float* __restrict__ fc2w,
                             const float* __restrict__ fc2b,
                             float* __restrict__ out) {
    int w = threadIdx.x >> 5;
    int lane = threadIdx.x & 31;
    int n = blockIdx.x * 4 + w;
    if (n >= N_NODES) return;
    float v = g_z[n * 64 + lane] * fc2w[lane]
            + g_z[n * 64 + lane + 32] * fc2w[lane + 32];
    #pragma unroll
    for (int o = 16; o; o >>= 1) v += __shfl_xor_sync(0xffffffffu, v, o);
    if (lane == 0) out[n] = v + fc2b[0];
}

// ============================================================================
// Launch — fork/join: setup chain + T-GEMM-0 on side stream, concurrent with
// l1 + cast_w2 + GEMM1 on the main (capture) stream.  (R13 configuration.)
// ============================================================================
extern "C" void kernel_launch(void* const* d_in, const int* in_sizes, int n_in,
                              void* d_out, int out_size) {
    const float* x     = (const float*)d_in[0];
    const void*  ei    = d_in[1];
    const float* attr  = (const float*)d_in[2];
    const float* fc1w  = (const float*)d_in[3];
    const float* fc1b  = (const float*)d_in[4];
    const float* kw1   = (const float*)d_in[5];
    const float* kb1   = (const float*)d_in[6];
    const float* kw2   = (const float*)d_in[7];
    const float* kb2   = (const float*)d_in[8];
    const float* kw3   = (const float*)d_in[9];
    const float* kb3   = (const float*)d_in[10];
    const float* root  = (const float*)d_in[11];
    const float* convb = (const float*)d_in[12];
    const float* fc2w  = (const float*)d_in[13];
    const float* fc2b  = (const float*)d_in[14];
    float* out = (float*)d_out;
    (void)in_sizes; (void)n_in; (void)out_size;

    static int init_done = 0;
    static __half *h1h, *h1l, *h2h, *h2l, *w2th, *w2tl, *k3th, *k3tl,
                  *zph, *zpl, *Th, *Tl;
    static cudaStream_t s1;
    static cudaEvent_t evFork, evJoin;
    if (!init_done) {
        cudaFuncSetAttribute(gemm_split_kernel<true>,
                             cudaFuncAttributeMaxDynamicSharedMemorySize,
                             GEMM_DSMEM);
        cudaFuncSetAttribute(gemm_split_kernel<false>,
                             cudaFuncAttributeMaxDynamicSharedMemorySize,
                             GEMM_DSMEM);
        cudaFuncSetAttribute(edge_mma_kernel,
                             cudaFuncAttributeMaxDynamicSharedMemorySize,
                             E2_SMEM);
        cudaGetSymbolAddress((void**)&h1h,  g_h1h);
        cudaGetSymbolAddress((void**)&h1l,  g_h1l);
        cudaGetSymbolAddress((void**)&h2h,  g_h2h);
        cudaGetSymbolAddress((void**)&h2l,  g_h2l);
        cudaGetSymbolAddress((void**)&w2th, g_w2th);
        cudaGetSymbolAddress((void**)&w2tl, g_w2tl);
        cudaGetSymbolAddress((void**)&k3th, g_k3th);
        cudaGetSymbolAddress((void**)&k3tl, g_k3tl);
        cudaGetSymbolAddress((void**)&zph,  g_zph);
        cudaGetSymbolAddress((void**)&zpl,  g_zpl);
        cudaGetSymbolAddress((void**)&Th,   g_Th);
        cudaGetSymbolAddress((void**)&Tl,   g_Tl);
        cudaStreamCreateWithFlags(&s1, cudaStreamNonBlocking);
        cudaEventCreateWithFlags(&evFork, cudaEventDisableTiming);
        cudaEventCreateWithFlags(&evJoin, cudaEventDisableTiming);
        init_done = 1;
    }

    // ---- fork: side stream s1 handles everything independent of h2 ----
    cudaEventRecord(evFork, 0);
    cudaStreamWaitEvent(s1, evFork, 0);

    // main stream: h2 production (single-sync GEMM — best at 2 CTA/SM)
    l1_kernel<<<N_EDGES, 256>>>(attr, kw1, kb1);
    cast_w2_kernel<<<(KDIM * KDIM + 255) / 256, 256>>>(kw2);
    gemm_split_kernel<true><<<dim3(KDIM / BN, N_EDGES / BM), 256, GEMM_DSMEM>>>(
        h1h, h1l, w2th, w2tl, h2h, h2l, kb2, KDIM, KDIM, 1);

    // side stream: graph setup + z0 + k3tt2 + first T-GEMM (double-sync)
    detect_kernel<<<1, 32, 0, s1>>>(ei);
    zero_z0_kernel<<<(N_NODES * WIDTH + 255) / 256, 256, 0, s1>>>(x, fc1w, fc1b);
    decode_count_kernel<<<N_EDGES / 256, 256, 0, s1>>>(ei);
    scan_kernel<<<1, 1024, 0, s1>>>();
    scatter_kernel<<<N_EDGES / 256, 256, 0, s1>>>();
    tilefill_kernel<<<N_NODES, 32, 0, s1>>>();
    k3tt2_kernel<<<(NT2 * WIDTH + 255) / 256, 256, 0, s1>>>(kw3);
    zsplit_kernel<<<(MPAD * WIDTH + 255) / 256, 256, 0, s1>>>();
    bz_kernel<<<N_NODES, 64, 0, s1>>>(kb3);
    gemm_split_kernel<false><<<dim3(NT2 / BN, MPAD / BM), 256, GEMM_DSMEM, s1>>>(
        zph, zpl, k3th, k3tl, Th, Tl, nullptr, NT2, WIDTH, 0);
    cudaEventRecord(evJoin, s1);

    // ---- join before first edge_mma ----
    cudaStreamWaitEvent(0, evJoin, 0);

    for (int d = 0; d < 6; d++) {
        if (d > 0) {
            // T[n, o*1024+j] = zp @ k3tt2^T : [1024 x 65536], K=64, hi/lo out
            gemm_split_kernel<false><<<dim3(NT2 / BN, MPAD / BM), 256, GEMM_DSMEM>>>(
                zph, zpl, k3th, k3tl, Th, Tl, nullptr, NT2, WIDTH, 0);
        }
        edge_mma_kernel<<<MAX_TILES, 256, E2_SMEM>>>();
        update_fused_kernel<<<N_NODES, 64>>>(root, convb, kb3);
    }

    final_kernel<<<(N_NODES + 3) / 4, 128>>>(fc2w, fc2b, out);
}

// round 16
// speedup vs baseline: 1.0626x; 1.0029x over previous
#include <cuda_runtime.h>
#include <cuda_fp16.h>
#include <cstdint>

// ============================================================================
// Problem constants
// ============================================================================
#define N_NODES 961
#define N_EDGES 32768
#define WIDTH   64
#define KDIM    1024
#define N3      4096   // WIDTH*WIDTH
#define MPAD    1024   // padded node count for T-GEMM
#define NT2     65536  // 64*1024 (o,j) pairs
#define MAX_TILES 1473 // <= N_NODES + N_EDGES/64

// ============================================================================
// Device scratch (sanctioned: __device__ globals, no runtime allocation)
// ============================================================================
__device__ __half g_h1h[(size_t)N_EDGES * KDIM];         //  64 MB
__device__ __half g_h1l[(size_t)N_EDGES * KDIM];         //  64 MB
__device__ __half g_h2h[(size_t)N_EDGES * KDIM];         //  64 MB
__device__ __half g_h2l[(size_t)N_EDGES * KDIM];         //  64 MB
__device__ __half g_Th [(size_t)MPAD * NT2];             // 128 MB  T[n][o][j] hi
__device__ __half g_Tl [(size_t)MPAD * NT2];             // 128 MB  T[n][o][j] lo
__device__ __half g_w2th[(size_t)KDIM * KDIM];           //   2 MB
__device__ __half g_w2tl[(size_t)KDIM * KDIM];           //   2 MB
__device__ __half g_k3th[(size_t)NT2 * WIDTH];           //   8 MB  k3tt2 hi
__device__ __half g_k3tl[(size_t)NT2 * WIDTH];           //   8 MB
__device__ __half g_zph[MPAD * WIDTH];
__device__ __half g_zpl[MPAD * WIDTH];
__device__ float  g_Bz [N_NODES * WIDTH];
__device__ float  g_z  [N_NODES * WIDTH];
__device__ float  g_agg[N_NODES * WIDTH];
__device__ float  g_cnt[N_NODES];
__device__ float  g_invcnt[N_NODES];
__device__ int    g_src[N_EDGES];
__device__ int    g_dst[N_EDGES];
__device__ int    g_srccnt[N_NODES];
__device__ int    g_scur[N_NODES];
__device__ int    g_srcptr[N_NODES + 1];
__device__ int    g_tileptr[N_NODES + 1];
__device__ int    g_eord[N_EDGES];
__device__ int    g_tilemap[MAX_TILES];
__device__ int    g_ntiles;
__device__ int    g_flag;

// ============================================================================
// PTX helpers (compute_100-safe: cp.async / ldmatrix / mma.sync only)
// ============================================================================
__device__ __forceinline__ uint32_t smem_u32(const void* smem_ptr) {
    uint32_t addr;
    asm("{ .reg .u64 tmp; cvta.to.shared.u64 tmp, %1; cvt.u32.u64 %0, tmp; }"
        : "=r"(addr) : "l"(smem_ptr));
    return addr;
}

__device__ __forceinline__ void cp_async16(uint32_t saddr, const void* gaddr) {
    asm volatile("cp.async.cg.shared.global [%0], [%1], 16;\n"
                 :: "r"(saddr), "l"(gaddr));
}
// Predicated: src_size=0 -> zero-fill the 16B destination.
__device__ __forceinline__ void cp_async16_pred(uint32_t saddr, const void* gaddr,
                                                int src_size) {
    asm volatile("cp.async.cg.shared.global [%0], [%1], 16, %2;\n"
                 :: "r"(saddr), "l"(gaddr), "r"(src_size));
}
__device__ __forceinline__ void cp_async_commit() {
    asm volatile("cp.async.commit_group;\n" ::: "memory");
}
template <int N>
__device__ __forceinline__ void cp_async_wait() {
    asm volatile("cp.async.wait_group %0;\n" :: "n"(N) : "memory");
}

#define LDSM4(r0, r1, r2, r3, addr) \
    asm volatile("ldmatrix.sync.aligned.m8n8.x4.shared.b16 {%0,%1,%2,%3}, [%4];" \
                 : "=r"(r0), "=r"(r1), "=r"(r2), "=r"(r3) : "r"(addr))

__device__ __forceinline__ void mma_16816(float* c, const uint32_t* a,
                                          uint32_t b0, uint32_t b1) {
    asm volatile(
        "mma.sync.aligned.m16n8k16.row.col.f32.f16.f16.f32 "
        "{%0,%1,%2,%3}, {%4,%5,%6,%7}, {%8,%9}, {%0,%1,%2,%3};"
        : "+f"(c[0]), "+f"(c[1]), "+f"(c[2]), "+f"(c[3])
        : "r"(a[0]), "r"(a[1]), "r"(a[2]), "r"(a[3]), "r"(b0), "r"(b1));
}

// ============================================================================
// Setup kernels
// ============================================================================

// h1 = relu(edge_attr @ k_w1 + b1), split hi/lo fp16 out
__global__ void l1_kernel(const float* __restrict__ attr,
                          const float* __restrict__ w1,
                          const float* __restrict__ b1) {
    int e = blockIdx.x;
    __shared__ float a[6];
    if (threadIdx.x < 6) a[threadIdx.x] = attr[e * 6 + threadIdx.x];
    __syncthreads();
    for (int j = threadIdx.x; j < KDIM; j += blockDim.x) {
        float acc = b1[j];
        #pragma unroll
        for (int i = 0; i < 6; i++) acc += a[i] * w1[i * KDIM + j];
        acc = fmaxf(acc, 0.f);
        __half hi = __float2half_rn(acc);
        g_h1h[(size_t)e * KDIM + j] = hi;
        g_h1l[(size_t)e * KDIM + j] = __float2half_rn(acc - __half2float(hi));
    }
}

// Detect whether edge_index buffer is int64 or int32.
__global__ void detect_kernel(const void* ei) {
    if (threadIdx.x == 0 && blockIdx.x == 0) {
        const long long* p = (const long long*)ei;
        int ok = 1;
        for (int i = 0; i < 64; i++) {
            long long v = p[i];
            if (v < 0 || v >= N_NODES) { ok = 0; break; }
        }
        g_flag = ok;   // 1 => int64, 0 => int32
    }
}

// w2t hi/lo: dst[n*1024 + k] = split( kw2[k*1024 + n] )
__global__ void cast_w2_kernel(const float* __restrict__ src) {
    int i = blockIdx.x * blockDim.x + threadIdx.x;
    if (i >= KDIM * KDIM) return;
    int n = i >> 10;
    int k = i & 1023;
    float v = src[k * KDIM + n];
    __half hi = __float2half_rn(v);
    g_w2th[i] = hi;
    g_w2tl[i] = __float2half_rn(v - __half2float(hi));
}

// Zero counters + compute z0 = x@fc1 + b.
__global__ void zero_z0_kernel(const float* __restrict__ x,
                               const float* __restrict__ w,
                               const float* __restrict__ b) {
    int i = blockIdx.x * blockDim.x + threadIdx.x;
    if (i < N_NODES) {
        g_cnt[i] = 0.f;
        g_srccnt[i] = 0;
        g_scur[i] = 0;
    }
    if (i < N_NODES * WIDTH) {
        int n = i >> 6, j = i & 63;
        g_agg[i] = 0.f;
        g_z[i] = x[n] * w[j] + b[j];
    }
}

// k3tt2 hi/lo (o-major): row r2 = o*1024 + j, col i:
//   k3tt2[r2*64 + i] = kw3[j*4096 + i*64 + o]
__global__ void k3tt2_kernel(const float* __restrict__ kw3) {
    int idx = blockIdx.x * blockDim.x + threadIdx.x;  // < 65536*64
    int r2 = idx >> 6;
    int i = idx & 63;
    int o = r2 >> 10;
    int j = r2 & 1023;
    float v = kw3[(size_t)j * N3 + i * 64 + o];
    __half hi = __float2half_rn(v);
    g_k3th[idx] = hi;
    g_k3tl[idx] = __float2half_rn(v - __half2float(hi));
}

// Decode edge_index, count dst (for mean) and src (for CSR).
__global__ void decode_count_kernel(const void* ei) {
    int e = blockIdx.x * blockDim.x + threadIdx.x;
    if (e >= N_EDGES) return;
    int s, d;
    if (g_flag) {
        const long long* p = (const long long*)ei;
        s = (int)p[e];
        d = (int)p[N_EDGES + e];
    } else {
        const int* p = (const int*)ei;
        s = p[e];
        d = p[N_EDGES + e];
    }
    g_src[e] = s;
    g_dst[e] = d;
    atomicAdd(&g_cnt[d], 1.0f);
    atomicAdd(&g_srccnt[s], 1);
}

// Scans: srccnt -> srcptr (exclusive), invcnt; 64-edge tile counts -> tileptr.
__global__ void scan_kernel() {
    __shared__ int s[1024];
    int tid = threadIdx.x;
    int v = (tid < N_NODES) ? g_srccnt[tid] : 0;
    s[tid] = v;
    __syncthreads();
    #pragma unroll
    for (int off = 1; off < 1024; off <<= 1) {
        int t = (tid >= off) ? s[tid - off] : 0;
        __syncthreads();
        s[tid] += t;
        __syncthreads();
    }
    if (tid < N_NODES) {
        g_srcptr[tid] = s[tid] - v;
        g_invcnt[tid] = 1.0f / fmaxf(g_cnt[tid], 1.0f);
    }
    if (tid == 0) g_srcptr[N_NODES] = N_EDGES;
    __syncthreads();

    int tc = (tid < N_NODES) ? ((v + 63) >> 6) : 0;
    s[tid] = tc;
    __syncthreads();
    #pragma unroll
    for (int off = 1; off < 1024; off <<= 1) {
        int t = (tid >= off) ? s[tid - off] : 0;
        __syncthreads();
        s[tid] += t;
        __syncthreads();
    }
    if (tid < N_NODES) g_tileptr[tid] = s[tid] - tc;
    if (tid == 1023) {
        g_tileptr[N_NODES] = s[1023];
        g_ntiles = s[1023];
    }
}

// Scatter edges into src-sorted order; fill tile map.
__global__ void scatter_kernel() {
    int e = blockIdx.x * blockDim.x + threadIdx.x;
    if (e >= N_EDGES) return;
    int s = g_src[e];
    int pos = g_srcptr[s] + atomicAdd(&g_scur[s], 1);
    g_eord[pos] = e;
}
__global__ void tilefill_kernel() {
    int n = blockIdx.x;
    int tp = g_tileptr[n];
    int tc = g_tileptr[n + 1] - tp;
    for (int t = threadIdx.x; t < tc; t += blockDim.x)
        g_tilemap[tp + t] = n | (t << 16);
}

// ============================================================================
// Split-fp16 3-pass GEMM:  C(hi,lo) = act(A @ BT^T [+ bias])
//   C = A_hi*B_hi + A_hi*B_lo + A_lo*B_hi  (fp32 accum), out split to fp16 pair
// CTA tile 128x128xBK32, 2-stage cp.async, 256 threads (4m x 2n).
// SINGLE_SYNC=true : single-barrier loop (best for 2-CTA/SM GEMM1 regime)
// SINGLE_SYNC=false: classic double-barrier loop (best for many-wave T-GEMM)
// ============================================================================
#define BM 128
#define BN 128
#define BK 32
#define LDA 40
#define STAGE_HALFS (512 * LDA)
#define STAGE_BYTES (STAGE_HALFS * 2) // 40960
#define GEMM_DSMEM (2 * STAGE_BYTES)  // 81920

#define OFF_AL (128 * LDA * 2)
#define OFF_BH (256 * LDA * 2)
#define OFF_BL (384 * LDA * 2)

template <bool SINGLE_SYNC>
__global__ void __launch_bounds__(256) gemm_split_kernel(
        const __half* __restrict__ Ah, const __half* __restrict__ Al,
        const __half* __restrict__ Bh, const __half* __restrict__ Bl,
        __half* __restrict__ Ch, __half* __restrict__ Cl,
        const float* __restrict__ bias, int N, int K, int relu) {
    extern __shared__ __align__(16) __half sm[];

    const int tid  = threadIdx.x;
    const int lane = tid & 31;
    const int wid  = tid >> 5;
    const int wm   = wid & 3;
    const int wn   = wid >> 2;
    const int bn   = blockIdx.x;
    const int bm   = blockIdx.y;

    const uint32_t sbase = smem_u32(sm);

    const int crow = tid >> 2;
    const int ccol = (tid & 3) * 8;
    const size_t arow = (size_t)(bm * BM + crow) * K + ccol;
    const __half* gAh0 = Ah + arow;
    const __half* gAh1 = gAh0 + (size_t)64 * K;
    const __half* gAl0 = Al + arow;
    const __half* gAl1 = gAl0 + (size_t)64 * K;
    const size_t brow = (size_t)(bn * BN + crow) * K + ccol;
    const __half* gBh0 = Bh + brow;
    const __half* gBh1 = gBh0 + (size_t)64 * K;
    const __half* gBl0 = Bl + brow;
    const __half* gBl1 = gBl0 + (size_t)64 * K;
    uint32_t so_[8];
    #pragma unroll
    for (int r = 0; r < 8; r++)
        so_[r] = ((crow + r * 64) * LDA + ccol) * 2;

    uint32_t aoff[2];
    #pragma unroll
    for (int mt = 0; mt < 2; mt++) {
        int r = wm * 32 + mt * 16 + (lane & 15);
        int c = (lane >> 4) << 3;
        aoff[mt] = (r * LDA + c) * 2;
    }
    uint32_t boff[4];
    #pragma unroll
    for (int tp = 0; tp < 4; tp++) {
        int r = wn * 64 + tp * 16 + ((lane >> 4) << 3) + (lane & 7);
        int c = ((lane >> 3) & 1) * 8;
        boff[tp] = OFF_BH + (r * LDA + c) * 2;
    }

    float acc[2][8][4];
    #pragma unroll
    for (int mt = 0; mt < 2; mt++)
        #pragma unroll
        for (int nt = 0; nt < 8; nt++)
            #pragma unroll
            for (int i = 0; i < 4; i++) acc[mt][nt][i] = 0.f;

    const int nkt = K / BK;

    #define G_LOAD(st, kt) do { \
        uint32_t so = sbase + (st) * STAGE_BYTES; \
        int go = (kt) * BK; \
        cp_async16(so + so_[0], gAh0 + go); \
        cp_async16(so + so_[1], gAh1 + go); \
        cp_async16(so + so_[2], gAl0 + go); \
        cp_async16(so + so_[3], gAl1 + go); \
        cp_async16(so + so_[4], gBh0 + go); \
        cp_async16(so + so_[5], gBh1 + go); \
        cp_async16(so + so_[6], gBl0 + go); \
        cp_async16(so + so_[7], gBl1 + go); \
    } while (0)

    G_LOAD(0, 0);
    cp_async_commit();

    for (int kt = 0; kt < nkt; kt++) {
        if (SINGLE_SYNC) {
            cp_async_wait<0>();
            __syncthreads();
            if (kt + 1 < nkt) {
                G_LOAD((kt + 1) & 1, kt + 1);
                cp_async_commit();
            }
        } else {
            if (kt + 1 < nkt) {
                G_LOAD((kt + 1) & 1, kt + 1);
                cp_async_commit();
                cp_async_wait<1>();
            } else {
                cp_async_wait<0>();
            }
            __syncthreads();
        }

        const uint32_t sb = sbase + (kt & 1) * STAGE_BYTES;
        #pragma unroll
        for (int kk = 0; kk < 2; kk++) {
            uint32_t ah[2][4], al[2][4];
            #pragma unroll
            for (int mt = 0; mt < 2; mt++) {
                LDSM4(ah[mt][0], ah[mt][1], ah[mt][2], ah[mt][3],
                      sb + aoff[mt] + kk * 32);
                LDSM4(al[mt][0], al[mt][1], al[mt][2], al[mt][3],
                      sb + OFF_AL + aoff[mt] + kk * 32);
            }
            uint32_t bh[4][4], bl[4][4];
            #pragma unroll
            for (int tp = 0; tp < 4; tp++) {
                LDSM4(bh[tp][0], bh[tp][1], bh[tp][2], bh[tp][3],
                      sb + boff[tp] + kk * 32);
                LDSM4(bl[tp][0], bl[tp][1], bl[tp][2], bl[tp][3],
                      sb + (OFF_BL - OFF_BH) + boff[tp] + kk * 32);
            }
            #pragma unroll
            for (int mt = 0; mt < 2; mt++)
                #pragma unroll
                for (int nt = 0; nt < 8; nt++) {
                    const uint32_t* bhp = bh[nt >> 1];
                    const uint32_t* blp = bl[nt >> 1];
                    uint32_t h0, h1, l0, l1;
                    if (nt & 1) { h0 = bhp[2]; h1 = bhp[3]; l0 = blp[2]; l1 = blp[3]; }
                    else        { h0 = bhp[0]; h1 = bhp[1]; l0 = blp[0]; l1 = blp[1]; }
                    mma_16816(acc[mt][nt], ah[mt], h0, h1);
                    mma_16816(acc[mt][nt], ah[mt], l0, l1);
                    mma_16816(acc[mt][nt], al[mt], h0, h1);
                }
        }
        if (!SINGLE_SYNC) __syncthreads();
    }
    #undef G_LOAD

    #pragma unroll
    for (int mt = 0; mt < 2; mt++) {
        int r0 = bm * BM + wm * 32 + mt * 16 + (lane >> 2);
        #pragma unroll
        for (int nt = 0; nt < 8; nt++) {
            int col = bn * BN + wn * 64 + nt * 8 + (lane & 3) * 2;
            float b0 = 0.f, b1 = 0.f;
            if (bias) { b0 = __ldg(bias + col); b1 = __ldg(bias + col + 1); }
            float v[4];
            v[0] = acc[mt][nt][0] + b0;
            v[1] = acc[mt][nt][1] + b1;
            v[2] = acc[mt][nt][2] + b0;
            v[3] = acc[mt][nt][3] + b1;
            if (relu) {
                v[0] = fmaxf(v[0], 0.f); v[1] = fmaxf(v[1], 0.f);
                v[2] = fmaxf(v[2], 0.f); v[3] = fmaxf(v[3], 0.f);
            }
            __half h0 = __float2half_rn(v[0]), h1 = __float2half_rn(v[1]);
            __half h2v = __float2half_rn(v[2]), h3 = __float2half_rn(v[3]);
            size_t o0 = (size_t)r0 * N + col;
            size_t o1 = (size_t)(r0 + 8) * N + col;
            *(__half2*)(Ch + o0) = __halves2half2(h0, h1);
            *(__half2*)(Ch + o1) = __halves2half2(h2v, h3);
            *(__half2*)(Cl + o0) = __halves2half2(
                __float2half_rn(v[0] - __half2float(h0)),
                __float2half_rn(v[1] - __half2float(h1)));
            *(__half2*)(Cl + o1) = __halves2half2(
                __float2half_rn(v[2] - __half2float(h2v)),
                __float2half_rn(v[3] - __half2float(h3)));
        }
    }
}

// ============================================================================
// Depth-loop kernels
// ============================================================================

// Split z into padded hi/lo fp16 (rows >= N_NODES -> 0). Initial use only.
__global__ void zsplit_kernel() {
    int i = blockIdx.x * blockDim.x + threadIdx.x;
    if (i >= MPAD * WIDTH) return;
    int n = i >> 6;
    float v = (n < N_NODES) ? g_z[i] : 0.f;
    __half hi = __float2half_rn(v);
    g_zph[i] = hi;
    g_zpl[i] = __float2half_rn(v - __half2float(hi));
}

// Bz[n,o] = sum_i z[n,i] * b3[i*64+o]. Initial use only.
__global__ void bz_kernel(const float* __restrict__ b3) {
    int n = blockIdx.x;
    int o = threadIdx.x;
    __shared__ float zs[64];
    zs[o] = g_z[n * 64 + o];
    __syncthreads();
    float acc = 0.f;
    #pragma unroll 8
    for (int i = 0; i < 64; i++) acc += zs[i] * b3[i * 64 + o];
    g_Bz[n * 64 + o] = acc;
}

// ============================================================================
// Edge-tile mma kernel: per tile (node n, 64 edges):
//   msg[64,64] = h2[rows,1024] @ T_n[64,1024]^T   (3-pass split mma)
//   agg[dst] += (msg + Bz[n]) * invcnt[dst]
// 256 threads = 8 warps (4m x 2n). BK=64, K=1024, double-sync 2-stage.
// smem rows (LDA=72): Ahi 0-63, Alo 64-127, Bhi 128-191, Blo 192-255
// ============================================================================
#define E2_LDA 72
#define E2_STAGE_BYTES (256 * E2_LDA * 2)   // 36864
#define E2_SMEM (2 * E2_STAGE_BYTES)        // 73728
#define E2_OFF_AL (64 * E2_LDA * 2)
#define E2_OFF_BH (128 * E2_LDA * 2)
#define E2_OFF_BL (192 * E2_LDA * 2)

__global__ void __launch_bounds__(256) edge_mma_kernel() {
    const int bid = blockIdx.x;
    if (bid >= g_ntiles) return;
    const int tm = g_tilemap[bid];
    const int n = tm & 0xFFFF;
    const int t = tm >> 16;
    const int base = g_srcptr[n];
    const int nE = g_srcptr[n + 1] - base;
    const int row0 = t * 64;

    extern __shared__ __align__(16) __half esm[];
    const uint32_t sbase = smem_u32(esm);

    const int tid  = threadIdx.x;
    const int lane = tid & 31;
    const int wid  = tid >> 5;
    const int wm   = wid & 3;        // 4 m-groups of 16 rows
    const int wn   = wid >> 2;       // 2 n-groups of 32 cols

    const int lrow = tid >> 2;
    const int lcol = (tid & 3) * 16;
    const int aslot = row0 + lrow;
    const int apred = (aslot < nE);
    const int asz = apred ? 16 : 0;
    const int e_a = apred ? g_eord[base + aslot] : 0;
    const __half* gAh = g_h2h + (size_t)e_a * KDIM + lcol;
    const __half* gAl = g_h2l + (size_t)e_a * KDIM + lcol;
    const __half* gBh = g_Th + (size_t)n * NT2 + lrow * KDIM + lcol;
    const __half* gBl = g_Tl + (size_t)n * NT2 + lrow * KDIM + lcol;
    const uint32_t sA = (lrow * E2_LDA + lcol) * 2;
    const uint32_t sB = ((lrow + 128) * E2_LDA + lcol) * 2;

    const uint32_t aoff = ((wm * 16 + (lane & 15)) * E2_LDA + ((lane >> 4) << 3)) * 2;
    uint32_t boff[2];
    #pragma unroll
    for (int tp = 0; tp < 2; tp++) {
        int r = 128 + wn * 32 + tp * 16 + ((lane >> 4) << 3) + (lane & 7);
        int c = ((lane >> 3) & 1) * 8;
        boff[tp] = (r * E2_LDA + c) * 2;
    }

    float acc[4][4];
    #pragma unroll
    for (int nt = 0; nt < 4; nt++)
        #pragma unroll
        for (int i = 0; i < 4; i++) acc[nt][i] = 0.f;

    #define E2_LOAD(st, kt) do { \
        uint32_t so = sbase + (st) * E2_STAGE_BYTES; \
        int ko = (kt) * 64; \
        cp_async16_pred(so + sA,      gAh + ko,     asz); \
        cp_async16_pred(so + sA + 16, gAh + ko + 8, asz); \
        cp_async16_pred(so + E2_OFF_AL + sA,      gAl + ko,     asz); \
        cp_async16_pred(so + E2_OFF_AL + sA + 16, gAl + ko + 8, asz); \
        cp_async16(so + sB,      gBh + ko); \
        cp_async16(so + sB + 16, gBh + ko + 8); \
        uint32_t sBl = sB + (E2_OFF_BL - E2_OFF_BH); \
        cp_async16(so + sBl,      gBl + ko); \
        cp_async16(so + sBl + 16, gBl + ko + 8); \
    } while (0)

    E2_LOAD(0, 0);
    cp_async_commit();

    for (int kt = 0; kt < 16; kt++) {
        if (kt + 1 < 16) {
            E2_LOAD((kt + 1) & 1, kt + 1);
            cp_async_commit();
            cp_async_wait<1>();
        } else {
            cp_async_wait<0>();
        }
        __syncthreads();

        const uint32_t sb = sbase + (kt & 1) * E2_STAGE_BYTES;
        #pragma unroll
        for (int kk = 0; kk < 4; kk++) {
            uint32_t ah[4], al[4];
            LDSM4(ah[0], ah[1], ah[2], ah[3], sb + aoff + kk * 32);
            LDSM4(al[0], al[1], al[2], al[3], sb + E2_OFF_AL + aoff + kk * 32);
            uint32_t bh[2][4], bl[2][4];
            #pragma unroll
            for (int tp = 0; tp < 2; tp++) {
                LDSM4(bh[tp][0], bh[tp][1], bh[tp][2], bh[tp][3],
                      sb + boff[tp] + kk * 32);
                LDSM4(bl[tp][0], bl[tp][1], bl[tp][2], bl[tp][3],
                      sb + (E2_OFF_BL - E2_OFF_BH) + boff[tp] + kk * 32);
            }
            #pragma unroll
            for (int nt = 0; nt < 4; nt++) {
                const uint32_t* bhp = bh[nt >> 1];
                const uint32_t* blp = bl[nt >> 1];
                uint32_t h0, h1, l0, l1;
                if (nt & 1) { h0 = bhp[2]; h1 = bhp[3]; l0 = blp[2]; l1 = blp[3]; }
                else        { h0 = bhp[0]; h1 = bhp[1]; l0 = blp[0]; l1 = blp[1]; }
                mma_16816(acc[nt], ah, h0, h1);
                mma_16816(acc[nt], ah, l0, l1);
                mma_16816(acc[nt], al, h0, h1);
            }
        }
        __syncthreads();
    }
    #undef E2_LOAD

    const int r1 = wm * 16 + (lane >> 2);
    const int r2 = r1 + 8;
    const int s1 = row0 + r1;
    const int s2 = row0 + r2;
    int e1 = -1, e2 = -1;
    float ic1 = 0.f, ic2 = 0.f;
    int d1 = 0, d2 = 0;
    if (s1 < nE) { e1 = g_eord[base + s1]; d1 = g_dst[e1]; ic1 = g_invcnt[d1]; }
    if (s2 < nE) { e2 = g_eord[base + s2]; d2 = g_dst[e2]; ic2 = g_invcnt[d2]; }

    #pragma unroll
    for (int nt = 0; nt < 4; nt++) {
        int col = wn * 32 + nt * 8 + (lane & 3) * 2;
        float bz0 = g_Bz[n * 64 + col];
        float bz1 = g_Bz[n * 64 + col + 1];
        if (e1 >= 0) {
            atomicAdd(g_agg + d1 * 64 + col,     (acc[nt][0] + bz0) * ic1);
            atomicAdd(g_agg + d1 * 64 + col + 1, (acc[nt][1] + bz1) * ic1);
        }
        if (e2 >= 0) {
            atomicAdd(g_agg + d2 * 64 + col,     (acc[nt][2] + bz0) * ic2);
            atomicAdd(g_agg + d2 * 64 + col + 1, (acc[nt][3] + bz1) * ic2);
        }
    }
}

// Fused: z = relu(agg + z@root + conv_b); agg=0.
// last==0: also write zp hi/lo + Bz for next iteration.
// last==1: skip those; compute out[n] = z@fc2_w + fc2_b instead.
__global__ void update_fused_kernel(const float* __restrict__ root,
                                    const float* __restrict__ convb,
                                    const float* __restrict__ b3,
                                    const float* __restrict__ fc2w,
                                    const float* __restrict__ fc2b,
                                    float* __restrict__ out,
                                    int last) {
    int n = blockIdx.x;
    int j = threadIdx.x;
    __shared__ float zr[64], zn[64];
    zr[j] = g_z[n * 64 + j];
    __syncthreads();
    float acc = g_agg[n * 64 + j] + convb[j];
    #pragma unroll 8
    for (int k = 0; k < 64; k++) acc += zr[k] * root[k * 64 + j];
    float z = fmaxf(acc, 0.f);
    g_z[n * 64 + j] = z;
    g_agg[n * 64 + j] = 0.f;
    if (!last) {
        __half hi = __float2half_rn(z);
        g_zph[n * 64 + j] = hi;
        g_zpl[n * 64 + j] = __float2half_rn(z - __half2float(hi));
        zn[j] = z;
        __syncthreads();
        float b = 0.f;
        #pragma unroll 8
        for (int i = 0; i < 64; i++) b += zn[i] * b3[i * 64 + j];
        g_Bz[n * 64 + j] = b;
    } else {
        // out[n] = z @ fc2_w + fc2_b, reduced across the 64 lanes (2 warps)
        float v = z * fc2w[j];
        #pragma unroll
        for (int o = 16; o; o >>= 1) v += __shfl_xor_sync(0xffffffffu, v, o);
        if ((j & 31) == 0) zn[j >> 5] = v;   // partial per warp
        __syncthreads();
        if (j == 0) out[n] = zn[0] + zn[1] + fc2b[0];
    }
}

// ============================================================================
// Launch — fork/join: setup chain + T-GEMM-0 on side stream, concurrent with
// l1 + GEMM1 on the main (capture) stream.  (R13 config + micro-bundle.)
// ============================================================================
extern "C" void kernel_launch(void* const* d_in, const int* in_sizes, int n_in,
                              void* d_out, int out_size) {
    const float* x     = (const float*)d_in[0];
    const void*  ei    = d_in[1];
    const float* attr  = (const float*)d_in[2];
    const float* fc1w  = (const float*)d_in[3];
    const float* fc1b  = (const float*)d_in[4];
    const float* kw1   = (const float*)d_in[5];
    const float* kb1   = (const float*)d_in[6];
    const float* kw2   = (const float*)d_in[7];
    const float* kb2   = (const float*)d_in[8];
    const float* kw3   = (const float*)d_in[9];
    const float* kb3   = (const float*)d_in[10];
    const float* root  = (const float*)d_in[11];
    const float* convb = (const float*)d_in[12];
    const float* fc2w  = (const float*)d_in[13];
    const float* fc2b  = (const float*)d_in[14];
    float* out = (float*)d_out;
    (void)in_sizes; (void)n_in; (void)out_size;

    static int init_done = 0;
    static __half *h1h, *h1l, *h2h, *h2l, *w2th, *w2tl, *k3th, *k3tl,
                  *zph, *zpl, *Th, *Tl;
    static cudaStream_t s1;
    static cudaEvent_t evFork, evJoin, evW2;
    if (!init_done) {
        cudaFuncSetAttribute(gemm_split_kernel<true>,
                             cudaFuncAttributeMaxDynamicSharedMemorySize,
                             GEMM_DSMEM);
        cudaFuncSetAttribute(gemm_split_kernel<false>,
                             cudaFuncAttributeMaxDynamicSharedMemorySize,
                             GEMM_DSMEM);
        cudaFuncSetAttribute(edge_mma_kernel,
                             cudaFuncAttributeMaxDynamicSharedMemorySize,
                             E2_SMEM);
        cudaGetSymbolAddress((void**)&h1h,  g_h1h);
        cudaGetSymbolAddress((void**)&h1l,  g_h1l);
        cudaGetSymbolAddress((void**)&h2h,  g_h2h);
        cudaGetSymbolAddress((void**)&h2l,  g_h2l);
        cudaGetSymbolAddress((void**)&w2th, g_w2th);
        cudaGetSymbolAddress((void**)&w2tl, g_w2tl);
        cudaGetSymbolAddress((void**)&k3th, g_k3th);
        cudaGetSymbolAddress((void**)&k3tl, g_k3tl);
        cudaGetSymbolAddress((void**)&zph,  g_zph);
        cudaGetSymbolAddress((void**)&zpl,  g_zpl);
        cudaGetSymbolAddress((void**)&Th,   g_Th);
        cudaGetSymbolAddress((void**)&Tl,   g_Tl);
        cudaStreamCreateWithFlags(&s1, cudaStreamNonBlocking);
        cudaEventCreateWithFlags(&evFork, cudaEventDisableTiming);
        cudaEventCreateWithFlags(&evJoin, cudaEventDisableTiming);
        cudaEventCreateWithFlags(&evW2, cudaEventDisableTiming);
        init_done = 1;
    }

    // ---- fork: side stream s1 handles everything independent of h2 ----
    cudaEventRecord(evFork, 0);
    cudaStreamWaitEvent(s1, evFork, 0);

    // side stream: cast_w2 first (needed by GEMM1), then graph setup + TG0
    cast_w2_kernel<<<(KDIM * KDIM + 255) / 256, 256, 0, s1>>>(kw2);
    cudaEventRecord(evW2, s1);
    detect_kernel<<<1, 32, 0, s1>>>(ei);
    zero_z0_kernel<<<(N_NODES * WIDTH + 255) / 256, 256, 0, s1>>>(x, fc1w, fc1b);
    decode_count_kernel<<<N_EDGES / 256, 256, 0, s1>>>(ei);
    scan_kernel<<<1, 1024, 0, s1>>>();
    scatter_kernel<<<N_EDGES / 256, 256, 0, s1>>>();
    tilefill_kernel<<<N_NODES, 32, 0, s1>>>();
    k3tt2_kernel<<<(NT2 * WIDTH + 255) / 256, 256, 0, s1>>>(kw3);
    zsplit_kernel<<<(MPAD * WIDTH + 255) / 256, 256, 0, s1>>>();
    bz_kernel<<<N_NODES, 64, 0, s1>>>(kb3);
    gemm_split_kernel<false><<<dim3(NT2 / BN, MPAD / BM), 256, GEMM_DSMEM, s1>>>(
        zph, zpl, k3th, k3tl, Th, Tl, nullptr, NT2, WIDTH, 0);
    cudaEventRecord(evJoin, s1);

    // main stream: l1 (overlaps cast_w2), wait for w2t, then GEMM1
    l1_kernel<<<N_EDGES, 256>>>(attr, kw1, kb1);
    cudaStreamWaitEvent(0, evW2, 0);
    gemm_split_kernel<true><<<dim3(KDIM / BN, N_EDGES / BM), 256, GEMM_DSMEM>>>(
        h1h, h1l, w2th, w2tl, h2h, h2l, kb2, KDIM, KDIM, 1);

    // ---- join before first edge_mma ----
    cudaStreamWaitEvent(0, evJoin, 0);

    for (int d = 0; d < 6; d++) {
        if (d > 0) {
            // T[n, o*1024+j] = zp @ k3tt2^T : [1024 x 65536], K=64, hi/lo out
            gemm_split_kernel<false><<<dim3(NT2 / BN, MPAD / BM), 256, GEMM_DSMEM>>>(
                zph, zpl, k3th, k3tl, Th, Tl, nullptr, NT2, WIDTH, 0);
        }
        edge_mma_kernel<<<MAX_TILES, 256, E2_SMEM>>>();
        update_fused_kernel<<<N_NODES, 64>>>(root, convb, kb3, fc2w, fc2b, out,
                                             d == 5 ? 1 : 0);
    }
}